// round 1
// baseline (speedup 1.0000x reference)
#include <cuda_runtime.h>
#include <math.h>

#define NRAYS 4096
#define NSAMP 256
#define NTOT  (NRAYS*NSAMP)
#define RES   128
#define RES3  (RES*RES*RES)
#define T0    0.2f
#define DT    (2.8f/255.0f)
#define ACT_SHIFT (-4.595119850134589f)

// scratch (allocation-free rule: __device__ globals)
__device__ float g_alpha[NTOT];
__device__ float g_rgb[3*NTOT];
__device__ float g_nrm[3*NTOT];

__device__ __forceinline__ unsigned long long pk2(float lo, float hi){
    unsigned long long r; asm("mov.b64 %0,{%1,%2};" : "=l"(r) : "f"(lo), "f"(hi)); return r;
}
__device__ __forceinline__ void up2(unsigned long long v, float &lo, float &hi){
    asm("mov.b64 {%0,%1},%2;" : "=f"(lo), "=f"(hi) : "l"(v));
}
__device__ __forceinline__ void fma2(unsigned long long &d, unsigned long long a, unsigned long long b){
    asm("fma.rn.f32x2 %0,%1,%2,%0;" : "+l"(d) : "l"(a), "l"(b));
}

// h[0..31] (64 packed floats) += v * row[0..63]
__device__ __forceinline__ void accum_row(unsigned long long *h, const float *row, float v){
    unsigned long long vv = pk2(v, v);
    const ulonglong2 *rw = (const ulonglong2*)row;
    #pragma unroll
    for (int j = 0; j < 16; j++){
        ulonglong2 q = rw[j];
        fma2(h[2*j],   vv, q.x);
        fma2(h[2*j+1], vv, q.y);
    }
}

// shared layout (floats): W0 3456 | W1 4096 | W2 4096 | W3 192 | b0 64 | b1 64 | b2 64 | b3 4
#define SM_W1 3456
#define SM_W2 7552
#define SM_W3 11648
#define SM_B0 11840
#define SM_B1 11904
#define SM_B2 11968
#define SM_B3 12032
#define SM_TOT 12040

__global__ __launch_bounds__(128) void k_persample(
    const float* __restrict__ rays_o, const float* __restrict__ rays_d,
    const float* __restrict__ viewdirs,
    const float* __restrict__ lat_grid, const float* __restrict__ nrm_grid,
    const float* __restrict__ W0, const float* __restrict__ b0,
    const float* __restrict__ W1, const float* __restrict__ b1,
    const float* __restrict__ W2, const float* __restrict__ b2,
    const float* __restrict__ W3, const float* __restrict__ b3)
{
    __shared__ __align__(16) float sm[SM_TOT];
    int tid = threadIdx.x;
    for (int i = tid; i < 3456; i += 128) sm[i]          = W0[i];
    for (int i = tid; i < 4096; i += 128) sm[SM_W1 + i]  = W1[i];
    for (int i = tid; i < 4096; i += 128) sm[SM_W2 + i]  = W2[i];
    for (int i = tid; i < 192;  i += 128) sm[SM_W3 + i]  = W3[i];
    if (tid < 64){ sm[SM_B0+tid] = b0[tid]; sm[SM_B1+tid] = b1[tid]; sm[SM_B2+tid] = b2[tid]; }
    if (tid < 3)  sm[SM_B3+tid] = b3[tid];
    __syncthreads();

    const float *sW0 = sm, *sW1 = sm+SM_W1, *sW2 = sm+SM_W2, *sW3 = sm+SM_W3;
    const float *sb1 = sm+SM_B1, *sb2 = sm+SM_B2, *sb3 = sm+SM_B3;

    int idx = blockIdx.x * 128 + tid;
    int r = idx >> 8, s = idx & 255;

    float ox = rays_o[r*3], oy = rays_o[r*3+1], oz = rays_o[r*3+2];
    float dx = rays_d[r*3], dy = rays_d[r*3+1], dz = rays_d[r*3+2];
    float dinv = 1.0f / sqrtf(dx*dx + dy*dy + dz*dz);
    dx *= dinv; dy *= dinv; dz *= dinv;

    float t  = T0 + (float)s * DT;
    float px = ox + dx*t, py = oy + dy*t, pz = oz + dz*t;

    bool inb = (px >= -1.0f) & (px <= 1.0f) & (py >= -1.0f) & (py <= 1.0f)
             & (pz >= -1.0f) & (pz <= 1.0f);
    if (!inb){
        g_alpha[idx] = 0.0f;
        g_rgb[idx] = 0.0f; g_rgb[NTOT+idx] = 0.0f; g_rgb[2*NTOT+idx] = 0.0f;
        g_nrm[idx] = 0.0f; g_nrm[NTOT+idx] = 0.0f; g_nrm[2*NTOT+idx] = 0.0f;
        return;
    }

    // trilinear setup (coords clipped to [0,1] then scaled by RES-1)
    float ux = fminf(fmaxf((px + 1.0f) * 0.5f, 0.0f), 1.0f) * 127.0f;
    float uy = fminf(fmaxf((py + 1.0f) * 0.5f, 0.0f), 1.0f) * 127.0f;
    float uz = fminf(fmaxf((pz + 1.0f) * 0.5f, 0.0f), 1.0f) * 127.0f;
    int x0 = min((int)floorf(ux), 126);
    int y0 = min((int)floorf(uy), 126);
    int z0 = min((int)floorf(uz), 126);
    float fx = ux - (float)x0, fy = uy - (float)y0, fz = uz - (float)z0;
    float gx = 1.0f - fx, gy = 1.0f - fy, gz = 1.0f - fz;
    float w000 = gx*gy*gz, w100 = fx*gy*gz, w010 = gx*fy*gz, w001 = gx*gy*fz;
    float w110 = fx*fy*gz, w101 = fx*gy*fz, w011 = gx*fy*fz, w111 = fx*fy*fz;

    int o000 = (x0*RES + y0)*RES + z0;
    int o100 = o000 + RES*RES, o010 = o000 + RES, o001 = o000 + 1;
    int o110 = o100 + RES,     o101 = o100 + 1,   o011 = o010 + 1;
    int o111 = o110 + 1;

    float lat[16];
    #pragma unroll
    for (int c = 0; c < 16; c++){
        const float *g = lat_grid + c*RES3;
        lat[c] = w000*__ldg(g+o000) + w100*__ldg(g+o100) + w010*__ldg(g+o010)
               + w001*__ldg(g+o001) + w110*__ldg(g+o110) + w101*__ldg(g+o101)
               + w011*__ldg(g+o011) + w111*__ldg(g+o111);
    }
    float nv[3];
    #pragma unroll
    for (int c = 0; c < 3; c++){
        const float *g = nrm_grid + c*RES3;
        nv[c] = w000*__ldg(g+o000) + w100*__ldg(g+o100) + w010*__ldg(g+o010)
              + w001*__ldg(g+o001) + w110*__ldg(g+o110) + w101*__ldg(g+o101)
              + w011*__ldg(g+o011) + w111*__ldg(g+o111);
    }
    float nx = nv[0], ny = nv[1], nz = nv[2];
    float nl = sqrtf(nx*nx + ny*ny + nz*nz);
    float ninv = 1.0f / fmaxf(nl, 1e-12f);
    nx *= ninv; ny *= ninv; nz *= ninv;

    // alpha = 1 - exp(-softplus(density + shift) * stepsize)
    float d0 = lat[0] + ACT_SHIFT;
    float sp = fmaxf(d0, 0.0f) + log1pf(expf(-fabsf(d0)));
    float alpha = 1.0f - expf(-sp * 0.5f);
    g_alpha[idx] = alpha;
    g_nrm[idx] = nx; g_nrm[NTOT+idx] = ny; g_nrm[2*NTOT+idx] = nz;

    // reflection dirs
    float vx = viewdirs[r*3], vy = viewdirs[r*3+1], vz = viewdirs[r*3+2];
    float vinv = 1.0f / sqrtf(vx*vx + vy*vy + vz*vz);
    vx *= vinv; vy *= vinv; vz *= vinv;
    float dot = -(vx*nx + vy*ny + vz*nz);
    float rdx = 2.0f*dot*nx + vx, rdy = 2.0f*dot*ny + vy, rdz = 2.0f*dot*nz + vz;

    // ---- MLP layer 0: stream 54 features into 64 packed accumulators ----
    unsigned long long h[32];
    {
        const unsigned long long *bb = (const unsigned long long*)(sm + SM_B0);
        #pragma unroll
        for (int j = 0; j < 32; j++) h[j] = bb[j];
    }
    #pragma unroll
    for (int c = 0; c < 15; c++) accum_row(h, sW0 + c*64, lat[c+1]);
    accum_row(h, sW0 + 15*64, rdx);
    accum_row(h, sW0 + 16*64, rdy);
    accum_row(h, sW0 + 17*64, rdz);
    {
        float f = 1.0f;
        #pragma unroll
        for (int k = 0; k < 6; k++){
            float sx, cx, sy, cy, sz, cz;
            sincosf(f*rdx, &sx, &cx);
            sincosf(f*rdy, &sy, &cy);
            sincosf(f*rdz, &sz, &cz);
            accum_row(h, sW0 + (18+3*k  )*64, sx);
            accum_row(h, sW0 + (18+3*k+1)*64, sy);
            accum_row(h, sW0 + (18+3*k+2)*64, sz);
            accum_row(h, sW0 + (36+3*k  )*64, cx);
            accum_row(h, sW0 + (36+3*k+1)*64, cy);
            accum_row(h, sW0 + (36+3*k+2)*64, cz);
            f *= 2.0f;
        }
    }
    float a[64];
    #pragma unroll
    for (int j = 0; j < 32; j++){
        float lo, hi; up2(h[j], lo, hi);
        a[2*j] = fmaxf(lo, 0.0f); a[2*j+1] = fmaxf(hi, 0.0f);
    }
    // ---- layer 1 ----
    {
        const unsigned long long *bb = (const unsigned long long*)sb1;
        #pragma unroll
        for (int j = 0; j < 32; j++) h[j] = bb[j];
    }
    #pragma unroll
    for (int i = 0; i < 64; i++) accum_row(h, sW1 + i*64, a[i]);
    #pragma unroll
    for (int j = 0; j < 32; j++){
        float lo, hi; up2(h[j], lo, hi);
        a[2*j] = fmaxf(lo, 0.0f); a[2*j+1] = fmaxf(hi, 0.0f);
    }
    // ---- layer 2 ----
    {
        const unsigned long long *bb = (const unsigned long long*)sb2;
        #pragma unroll
        for (int j = 0; j < 32; j++) h[j] = bb[j];
    }
    #pragma unroll
    for (int i = 0; i < 64; i++) accum_row(h, sW2 + i*64, a[i]);
    #pragma unroll
    for (int j = 0; j < 32; j++){
        float lo, hi; up2(h[j], lo, hi);
        a[2*j] = fmaxf(lo, 0.0f); a[2*j+1] = fmaxf(hi, 0.0f);
    }
    // ---- layer 3: 64 -> 3 + sigmoid ----
    float q0 = sb3[0], q1 = sb3[1], q2 = sb3[2];
    #pragma unroll
    for (int i = 0; i < 64; i++){
        float v = a[i];
        q0 += v * sW3[i*3];
        q1 += v * sW3[i*3+1];
        q2 += v * sW3[i*3+2];
    }
    q0 = 1.0f / (1.0f + expf(-q0));
    q1 = 1.0f / (1.0f + expf(-q1));
    q2 = 1.0f / (1.0f + expf(-q2));
    g_rgb[idx] = q0; g_rgb[NTOT+idx] = q1; g_rgb[2*NTOT+idx] = q2;
}

// warp-per-ray: multiplicative scan for alphainv cumprod + composite
__global__ __launch_bounds__(256) void k_perray(float* __restrict__ out)
{
    int r    = (blockIdx.x * 256 + threadIdx.x) >> 5;
    int lane = threadIdx.x & 31;
    if (r >= NRAYS) return;

    float *o_rgb   = out;
    float *o_depth = out + 12288;
    float *o_disp  = out + 16384;
    float *o_acc   = out + 20480;
    float *o_nrm   = out + 24576;
    float *o_w     = out + 36864;
    float *o_ai    = out + 1085440;

    float P = 1.0f;
    float sr0=0.f, sr1=0.f, sr2=0.f, sd=0.f, sa=0.f, sn0=0.f, sn1=0.f, sn2=0.f;

    #pragma unroll 1
    for (int c = 0; c < 8; c++){
        int s   = c*32 + lane;
        int idx = (r << 8) + s;
        float alp = g_alpha[idx];
        float v   = fmaxf(1.0f - alp, 1e-10f);
        #pragma unroll
        for (int off = 1; off < 32; off <<= 1){
            float o = __shfl_up_sync(0xffffffffu, v, off);
            if (lane >= off) v *= o;
        }
        float pv   = __shfl_up_sync(0xffffffffu, v, 1);
        float excl = lane ? P * pv : P;
        float incl = P * v;
        float w    = alp * excl;
        o_w[idx]            = w;
        o_ai[r*257 + 1 + s] = incl;
        float t = T0 + (float)s * DT;
        sd += w * t; sa += w;
        sr0 += w * g_rgb[idx]; sr1 += w * g_rgb[NTOT+idx]; sr2 += w * g_rgb[2*NTOT+idx];
        sn0 += w * g_nrm[idx]; sn1 += w * g_nrm[NTOT+idx]; sn2 += w * g_nrm[2*NTOT+idx];
        P = __shfl_sync(0xffffffffu, incl, 31);
    }
    #pragma unroll
    for (int off = 16; off; off >>= 1){
        sr0 += __shfl_xor_sync(0xffffffffu, sr0, off);
        sr1 += __shfl_xor_sync(0xffffffffu, sr1, off);
        sr2 += __shfl_xor_sync(0xffffffffu, sr2, off);
        sd  += __shfl_xor_sync(0xffffffffu, sd,  off);
        sa  += __shfl_xor_sync(0xffffffffu, sa,  off);
        sn0 += __shfl_xor_sync(0xffffffffu, sn0, off);
        sn1 += __shfl_xor_sync(0xffffffffu, sn1, off);
        sn2 += __shfl_xor_sync(0xffffffffu, sn2, off);
    }
    if (lane == 0){
        o_rgb[r*3]   = sr0 + P;   // BG = 1.0
        o_rgb[r*3+1] = sr1 + P;
        o_rgb[r*3+2] = sr2 + P;
        float dm = sd + P * 3.0f; // FAR
        o_depth[r] = dm;
        o_disp[r]  = 1.0f / dm;
        o_acc[r]   = sa;
        o_nrm[r*3]   = sn0;
        o_nrm[r*3+1] = sn1;
        o_nrm[r*3+2] = sn2;
        o_ai[r*257]  = 1.0f;
    }
}

extern "C" void kernel_launch(void* const* d_in, const int* in_sizes, int n_in,
                              void* d_out, int out_size)
{
    const float* rays_o   = (const float*)d_in[0];
    const float* rays_d   = (const float*)d_in[1];
    const float* viewdirs = (const float*)d_in[2];
    const float* lat_grid = (const float*)d_in[3];
    const float* nrm_grid = (const float*)d_in[4];
    const float* W0 = (const float*)d_in[5];
    const float* b0 = (const float*)d_in[6];
    const float* W1 = (const float*)d_in[7];
    const float* b1 = (const float*)d_in[8];
    const float* W2 = (const float*)d_in[9];
    const float* b2 = (const float*)d_in[10];
    const float* W3 = (const float*)d_in[11];
    const float* b3 = (const float*)d_in[12];

    k_persample<<<NTOT/128, 128>>>(rays_o, rays_d, viewdirs, lat_grid, nrm_grid,
                                   W0, b0, W1, b1, W2, b2, W3, b3);
    k_perray<<<NRAYS*32/256, 256>>>((float*)d_out);
}

// round 3
// speedup vs baseline: 2.2659x; 2.2659x over previous
#include <cuda_runtime.h>
#include <cuda_bf16.h>
#include <math.h>
#include <stdint.h>

#define NRAYS 4096
#define NSAMP 256
#define NTOT  (NRAYS*NSAMP)
#define STRIDE (NTOT + 128)
#define RES   128
#define RES3  (RES*RES*RES)
#define T0    0.2f
#define DT    (2.8f/255.0f)
#define ACT_SHIFT (-4.595119850134589f)

// ---------------- scratch ----------------------------------------------------
__device__ float    g_alpha[NTOT];
__device__ float    g_rgb[3*NTOT];      // only in-box entries written; rest stay 0
__device__ float    g_nrm[3*NTOT];
__device__ uint32_t g_feat[64*STRIDE];  // (hi bf16 | lo bf16 << 16), column-major
__device__ int      g_sidx[STRIDE];
__device__ int      g_count;

// ---------------- kernel 1: featurize + compact ------------------------------
__device__ __forceinline__ void put_feat(int k, int pos, float v){
    __nv_bfloat16 h = __float2bfloat16(v);
    float hv = __bfloat162float(h);
    __nv_bfloat16 l = __float2bfloat16(v - hv);
    g_feat[k*STRIDE + pos] = (uint32_t)__bfloat16_as_ushort(h)
                           | ((uint32_t)__bfloat16_as_ushort(l) << 16);
}

__global__ __launch_bounds__(128) void k_feat(
    const float* __restrict__ rays_o, const float* __restrict__ rays_d,
    const float* __restrict__ viewdirs,
    const float* __restrict__ lat_grid, const float* __restrict__ nrm_grid)
{
    int idx  = blockIdx.x * 128 + threadIdx.x;
    int r    = idx >> 8, s = idx & 255;
    int lane = threadIdx.x & 31;

    float ox = rays_o[r*3], oy = rays_o[r*3+1], oz = rays_o[r*3+2];
    float dx = rays_d[r*3], dy = rays_d[r*3+1], dz = rays_d[r*3+2];
    float dinv = 1.0f / sqrtf(dx*dx + dy*dy + dz*dz);
    dx *= dinv; dy *= dinv; dz *= dinv;

    float t  = T0 + (float)s * DT;
    float px = ox + dx*t, py = oy + dy*t, pz = oz + dz*t;

    bool inb = (px >= -1.0f) & (px <= 1.0f) & (py >= -1.0f) & (py <= 1.0f)
             & (pz >= -1.0f) & (pz <= 1.0f);

    unsigned mask = __ballot_sync(0xffffffffu, inb);
    int base = 0;
    if (mask){
        if (lane == 0) base = atomicAdd(&g_count, __popc(mask));
        base = __shfl_sync(0xffffffffu, base, 0);
    }
    if (!inb){ g_alpha[idx] = 0.0f; return; }
    int pos = base + __popc(mask & ((1u << lane) - 1u));
    g_sidx[pos] = idx;

    float ux = fminf(fmaxf((px + 1.0f) * 0.5f, 0.0f), 1.0f) * 127.0f;
    float uy = fminf(fmaxf((py + 1.0f) * 0.5f, 0.0f), 1.0f) * 127.0f;
    float uz = fminf(fmaxf((pz + 1.0f) * 0.5f, 0.0f), 1.0f) * 127.0f;
    int x0 = min((int)floorf(ux), 126);
    int y0 = min((int)floorf(uy), 126);
    int z0 = min((int)floorf(uz), 126);
    float fx = ux - (float)x0, fy = uy - (float)y0, fz = uz - (float)z0;
    float gx = 1.0f - fx, gy = 1.0f - fy, gz = 1.0f - fz;
    float w000 = gx*gy*gz, w100 = fx*gy*gz, w010 = gx*fy*gz, w001 = gx*gy*fz;
    float w110 = fx*fy*gz, w101 = fx*gy*fz, w011 = gx*fy*fz, w111 = fx*fy*fz;

    int o000 = (x0*RES + y0)*RES + z0;
    int o100 = o000 + RES*RES, o010 = o000 + RES, o001 = o000 + 1;
    int o110 = o100 + RES,     o101 = o100 + 1,   o011 = o010 + 1;
    int o111 = o110 + 1;

    float lat[16];
    #pragma unroll
    for (int c = 0; c < 16; c++){
        const float *g = lat_grid + c*RES3;
        lat[c] = w000*__ldg(g+o000) + w100*__ldg(g+o100) + w010*__ldg(g+o010)
               + w001*__ldg(g+o001) + w110*__ldg(g+o110) + w101*__ldg(g+o101)
               + w011*__ldg(g+o011) + w111*__ldg(g+o111);
    }
    float nv[3];
    #pragma unroll
    for (int c = 0; c < 3; c++){
        const float *g = nrm_grid + c*RES3;
        nv[c] = w000*__ldg(g+o000) + w100*__ldg(g+o100) + w010*__ldg(g+o010)
              + w001*__ldg(g+o001) + w110*__ldg(g+o110) + w101*__ldg(g+o101)
              + w011*__ldg(g+o011) + w111*__ldg(g+o111);
    }
    float nx = nv[0], ny = nv[1], nz = nv[2];
    float nl = sqrtf(nx*nx + ny*ny + nz*nz);
    float ninv = 1.0f / fmaxf(nl, 1e-12f);
    nx *= ninv; ny *= ninv; nz *= ninv;

    float d0 = lat[0] + ACT_SHIFT;
    float sp = fmaxf(d0, 0.0f) + log1pf(expf(-fabsf(d0)));
    g_alpha[idx] = 1.0f - expf(-sp * 0.5f);
    g_nrm[idx] = nx; g_nrm[NTOT+idx] = ny; g_nrm[2*NTOT+idx] = nz;

    float vx = viewdirs[r*3], vy = viewdirs[r*3+1], vz = viewdirs[r*3+2];
    float vinv = 1.0f / sqrtf(vx*vx + vy*vy + vz*vz);
    vx *= vinv; vy *= vinv; vz *= vinv;
    float dot = -(vx*nx + vy*ny + vz*nz);
    float rdx = 2.0f*dot*nx + vx, rdy = 2.0f*dot*ny + vy, rdz = 2.0f*dot*nz + vz;

    #pragma unroll
    for (int c = 0; c < 15; c++) put_feat(c, pos, lat[c+1]);
    put_feat(15, pos, rdx); put_feat(16, pos, rdy); put_feat(17, pos, rdz);
    float f = 1.0f;
    #pragma unroll
    for (int k = 0; k < 6; k++){
        float sx, cx, sy, cy, sz, cz;
        sincosf(f*rdx, &sx, &cx);
        sincosf(f*rdy, &sy, &cy);
        sincosf(f*rdz, &sz, &cz);
        put_feat(18+3*k,   pos, sx); put_feat(18+3*k+1, pos, sy); put_feat(18+3*k+2, pos, sz);
        put_feat(36+3*k,   pos, cx); put_feat(36+3*k+1, pos, cy); put_feat(36+3*k+2, pos, cz);
        f *= 2.0f;
    }
}

// ---------------- kernel 2: HMMA (mma.sync bf16) MLP -------------------------
// SMEM (bytes): A rows padded to 72 bf16 (144B) for conflict-free fragments
#define A_HI     0
#define A_LO     18432
#define B_OFF(L,s) (36864 + ((L)*2+(s))*9216)
#define W3_OFF   92160
#define B012_OFF 92928
#define B3_OFF   93696
#define SMEM_SZ  93712

__device__ __forceinline__ void mma_bf16(float* d, uint32_t a0, uint32_t a1,
                                         uint32_t a2, uint32_t a3,
                                         uint32_t b0, uint32_t b1){
    asm volatile(
        "mma.sync.aligned.m16n8k16.row.col.f32.bf16.bf16.f32 "
        "{%0,%1,%2,%3}, {%4,%5,%6,%7}, {%8,%9}, {%0,%1,%2,%3};"
        : "+f"(d[0]), "+f"(d[1]), "+f"(d[2]), "+f"(d[3])
        : "r"(a0), "r"(a1), "r"(a2), "r"(a3), "r"(b0), "r"(b1));
}

__device__ __forceinline__ void split_bf16(float v, unsigned short &h, unsigned short &l){
    __nv_bfloat16 hb = __float2bfloat16(v);
    float hv = __bfloat162float(hb);
    __nv_bfloat16 lb = __float2bfloat16(v - hv);
    h = __bfloat16_as_ushort(hb);
    l = __bfloat16_as_ushort(lb);
}

__global__ __launch_bounds__(128) void k_mlp(
    const float* __restrict__ W0, const float* __restrict__ b0,
    const float* __restrict__ W1, const float* __restrict__ b1,
    const float* __restrict__ W2, const float* __restrict__ b2,
    const float* __restrict__ W3, const float* __restrict__ b3)
{
    extern __shared__ __align__(16) char smem[];
    int tid = threadIdx.x, wid = tid >> 5, lane = tid & 31;
    int gq = lane >> 2, tig = lane & 3;     // groupID, thread-in-group
    int wbase = wid * 32;

    // ---- preload weights: B[n][k] = W[k][n], hi/lo split, row pad 72 bf16 ----
    for (int i = tid; i < 4096; i += 128){
        int n = i >> 6, k = i & 63;
        int off = n*144 + 2*k;
        float v0 = (k < 54) ? W0[k*64 + n] : 0.0f;
        float v1 = W1[k*64 + n];
        float v2 = W2[k*64 + n];
        float vs[3] = {v0, v1, v2};
        #pragma unroll
        for (int L = 0; L < 3; L++){
            unsigned short h, l;
            split_bf16(vs[L], h, l);
            *(unsigned short*)(smem + B_OFF(L,0) + off) = h;
            *(unsigned short*)(smem + B_OFF(L,1) + off) = l;
        }
    }
    for (int i = tid; i < 192; i += 128) *(float*)(smem + W3_OFF + 4*i) = W3[i];
    if (tid < 64){
        *(float*)(smem + B012_OFF        + 4*tid) = b0[tid];
        *(float*)(smem + B012_OFF + 256  + 4*tid) = b1[tid];
        *(float*)(smem + B012_OFF + 512  + 4*tid) = b2[tid];
    }
    if (tid < 3) *(float*)(smem + B3_OFF + 4*tid) = b3[tid];
    __syncthreads();

    int cnt    = g_count;
    int ntiles = (cnt + 127) >> 7;

    for (int tile = blockIdx.x; tile < ntiles; tile += gridDim.x){
        int tbase = tile << 7;

        // ---- load A tile: 128 rows x 64 k, split hi/lo ----
        for (int i = tid; i < 8192; i += 128){
            int rr = i & 127, k = i >> 7;
            uint32_t v = g_feat[k*STRIDE + tbase + rr];
            int off = rr*144 + 2*k;
            *(unsigned short*)(smem + A_HI + off) = (unsigned short)(v & 0xffffu);
            *(unsigned short*)(smem + A_LO + off) = (unsigned short)(v >> 16);
        }
        __syncthreads();

        float acc[2][8][4];
        float rgbq[4][3];   // layer-3 partials per row-slot

        #pragma unroll 1
        for (int L = 0; L < 3; L++){
            #pragma unroll
            for (int m = 0; m < 2; m++)
                #pragma unroll
                for (int n = 0; n < 8; n++)
                    #pragma unroll
                    for (int j = 0; j < 4; j++) acc[m][n][j] = 0.0f;

            #pragma unroll 1
            for (int p = 0; p < 3; p++){
                const char* Ab = smem + ((p == 2) ? A_LO : A_HI);
                const char* Bb = smem + B_OFF(L, (p == 1) ? 1 : 0);
                #pragma unroll
                for (int ks = 0; ks < 4; ks++){
                    uint32_t a[2][4];
                    #pragma unroll
                    for (int m = 0; m < 2; m++){
                        const char* pr  = Ab + (wbase + m*16 + gq)*144 + 4*tig + 32*ks;
                        const char* pr8 = pr + 8*144;
                        a[m][0] = *(const uint32_t*)(pr);
                        a[m][1] = *(const uint32_t*)(pr8);
                        a[m][2] = *(const uint32_t*)(pr + 16);
                        a[m][3] = *(const uint32_t*)(pr8 + 16);
                    }
                    #pragma unroll
                    for (int n = 0; n < 8; n++){
                        const char* pb = Bb + (n*8 + gq)*144 + 4*tig + 32*ks;
                        uint32_t bb0 = *(const uint32_t*)(pb);
                        uint32_t bb1 = *(const uint32_t*)(pb + 16);
                        mma_bf16(acc[0][n], a[0][0], a[0][1], a[0][2], a[0][3], bb0, bb1);
                        mma_bf16(acc[1][n], a[1][0], a[1][1], a[1][2], a[1][3], bb0, bb1);
                    }
                }
            }

            if (L < 2){
                const float* bias = (const float*)(smem + B012_OFF + L*256);
                #pragma unroll
                for (int m = 0; m < 2; m++){
                    int r0 = wbase + m*16 + gq;
                    #pragma unroll
                    for (int n = 0; n < 8; n++){
                        int col0 = n*8 + 2*tig;
                        float v0 = fmaxf(acc[m][n][0] + bias[col0],   0.0f);
                        float v1 = fmaxf(acc[m][n][1] + bias[col0+1], 0.0f);
                        float v2 = fmaxf(acc[m][n][2] + bias[col0],   0.0f);
                        float v3 = fmaxf(acc[m][n][3] + bias[col0+1], 0.0f);
                        unsigned short h0,l0,h1,l1,h2,l2,h3,l3;
                        split_bf16(v0,h0,l0); split_bf16(v1,h1,l1);
                        split_bf16(v2,h2,l2); split_bf16(v3,h3,l3);
                        int off0 = r0*144 + 4*tig + 16*n;
                        int off1 = off0 + 8*144;
                        *(uint32_t*)(smem + A_HI + off0) = (uint32_t)h0 | ((uint32_t)h1 << 16);
                        *(uint32_t*)(smem + A_LO + off0) = (uint32_t)l0 | ((uint32_t)l1 << 16);
                        *(uint32_t*)(smem + A_HI + off1) = (uint32_t)h2 | ((uint32_t)h3 << 16);
                        *(uint32_t*)(smem + A_LO + off1) = (uint32_t)l2 | ((uint32_t)l3 << 16);
                    }
                }
            } else {
                // ---- layer 3 from fragments: 64 -> 3 ----
                const float* bias = (const float*)(smem + B012_OFF + 512);
                const float* w3   = (const float*)(smem + W3_OFF);
                #pragma unroll
                for (int sl = 0; sl < 4; sl++){ rgbq[sl][0]=0.f; rgbq[sl][1]=0.f; rgbq[sl][2]=0.f; }
                #pragma unroll
                for (int m = 0; m < 2; m++)
                    #pragma unroll
                    for (int n = 0; n < 8; n++){
                        int col0 = n*8 + 2*tig;
                        float v0 = fmaxf(acc[m][n][0] + bias[col0],   0.0f);
                        float v1 = fmaxf(acc[m][n][1] + bias[col0+1], 0.0f);
                        float v2 = fmaxf(acc[m][n][2] + bias[col0],   0.0f);
                        float v3 = fmaxf(acc[m][n][3] + bias[col0+1], 0.0f);
                        #pragma unroll
                        for (int c = 0; c < 3; c++){
                            rgbq[2*m  ][c] += v0*w3[col0*3+c] + v1*w3[(col0+1)*3+c];
                            rgbq[2*m+1][c] += v2*w3[col0*3+c] + v3*w3[(col0+1)*3+c];
                        }
                    }
            }
        }

        // reduce layer-3 partials across the 4 lanes sharing gq
        #pragma unroll
        for (int sl = 0; sl < 4; sl++)
            #pragma unroll
            for (int c = 0; c < 3; c++){
                float v = rgbq[sl][c];
                v += __shfl_xor_sync(0xffffffffu, v, 1);
                v += __shfl_xor_sync(0xffffffffu, v, 2);
                rgbq[sl][c] = v;
            }
        if (tig == 0){
            const float* bb3 = (const float*)(smem + B3_OFF);
            #pragma unroll
            for (int sl = 0; sl < 4; sl++){
                int m = sl >> 1, h = sl & 1;
                int gi = tbase + wbase + m*16 + gq + 8*h;
                if (gi < cnt){
                    int sidx = g_sidx[gi];
                    g_rgb[sidx]        = 1.0f/(1.0f + expf(-(rgbq[sl][0] + bb3[0])));
                    g_rgb[NTOT+sidx]   = 1.0f/(1.0f + expf(-(rgbq[sl][1] + bb3[1])));
                    g_rgb[2*NTOT+sidx] = 1.0f/(1.0f + expf(-(rgbq[sl][2] + bb3[2])));
                }
            }
        }
        __syncthreads();
    }
}

// ---------------- kernel 3: warp-per-ray composite ---------------------------
__global__ __launch_bounds__(256) void k_perray(float* __restrict__ out)
{
    if (blockIdx.x == 0 && threadIdx.x == 0) g_count = 0;  // reset for next replay
    int r    = (blockIdx.x * 256 + threadIdx.x) >> 5;
    int lane = threadIdx.x & 31;
    if (r >= NRAYS) return;

    float *o_rgb   = out;
    float *o_depth = out + 12288;
    float *o_disp  = out + 16384;
    float *o_acc   = out + 20480;
    float *o_nrm   = out + 24576;
    float *o_w     = out + 36864;
    float *o_ai    = out + 1085440;

    float P = 1.0f;
    float sr0=0.f, sr1=0.f, sr2=0.f, sd=0.f, sa=0.f, sn0=0.f, sn1=0.f, sn2=0.f;

    #pragma unroll 1
    for (int c = 0; c < 8; c++){
        int s   = c*32 + lane;
        int idx = (r << 8) + s;
        float alp = g_alpha[idx];
        float v   = fmaxf(1.0f - alp, 1e-10f);
        #pragma unroll
        for (int off = 1; off < 32; off <<= 1){
            float o = __shfl_up_sync(0xffffffffu, v, off);
            if (lane >= off) v *= o;
        }
        float pv   = __shfl_up_sync(0xffffffffu, v, 1);
        float excl = lane ? P * pv : P;
        float incl = P * v;
        float w    = alp * excl;
        o_w[idx]            = w;
        o_ai[r*257 + 1 + s] = incl;
        float t = T0 + (float)s * DT;
        sd += w * t; sa += w;
        sr0 += w * g_rgb[idx]; sr1 += w * g_rgb[NTOT+idx]; sr2 += w * g_rgb[2*NTOT+idx];
        sn0 += w * g_nrm[idx]; sn1 += w * g_nrm[NTOT+idx]; sn2 += w * g_nrm[2*NTOT+idx];
        P = __shfl_sync(0xffffffffu, incl, 31);
    }
    #pragma unroll
    for (int off = 16; off; off >>= 1){
        sr0 += __shfl_xor_sync(0xffffffffu, sr0, off);
        sr1 += __shfl_xor_sync(0xffffffffu, sr1, off);
        sr2 += __shfl_xor_sync(0xffffffffu, sr2, off);
        sd  += __shfl_xor_sync(0xffffffffu, sd,  off);
        sa  += __shfl_xor_sync(0xffffffffu, sa,  off);
        sn0 += __shfl_xor_sync(0xffffffffu, sn0, off);
        sn1 += __shfl_xor_sync(0xffffffffu, sn1, off);
        sn2 += __shfl_xor_sync(0xffffffffu, sn2, off);
    }
    if (lane == 0){
        o_rgb[r*3]   = sr0 + P;
        o_rgb[r*3+1] = sr1 + P;
        o_rgb[r*3+2] = sr2 + P;
        float dm = sd + P * 3.0f;
        o_depth[r] = dm;
        o_disp[r]  = 1.0f / dm;
        o_acc[r]   = sa;
        o_nrm[r*3]   = sn0;
        o_nrm[r*3+1] = sn1;
        o_nrm[r*3+2] = sn2;
        o_ai[r*257]  = 1.0f;
    }
}

extern "C" void kernel_launch(void* const* d_in, const int* in_sizes, int n_in,
                              void* d_out, int out_size)
{
    const float* rays_o   = (const float*)d_in[0];
    const float* rays_d   = (const float*)d_in[1];
    const float* viewdirs = (const float*)d_in[2];
    const float* lat_grid = (const float*)d_in[3];
    const float* nrm_grid = (const float*)d_in[4];
    const float* W0 = (const float*)d_in[5];
    const float* b0 = (const float*)d_in[6];
    const float* W1 = (const float*)d_in[7];
    const float* b1 = (const float*)d_in[8];
    const float* W2 = (const float*)d_in[9];
    const float* b2 = (const float*)d_in[10];
    const float* W3 = (const float*)d_in[11];
    const float* b3 = (const float*)d_in[12];

    static int smem_set = 0;
    if (!smem_set){
        cudaFuncSetAttribute(k_mlp, cudaFuncAttributeMaxDynamicSharedMemorySize, SMEM_SZ);
        smem_set = 1;
    }

    k_feat<<<NTOT/128, 128>>>(rays_o, rays_d, viewdirs, lat_grid, nrm_grid);
    k_mlp<<<296, 128, SMEM_SZ>>>(W0, b0, W1, b1, W2, b2, W3, b3);
    k_perray<<<NRAYS*32/256, 256>>>((float*)d_out);
}

// round 4
// speedup vs baseline: 2.3477x; 1.0361x over previous
#include <cuda_runtime.h>
#include <cuda_fp16.h>
#include <math.h>
#include <stdint.h>

#define NRAYS 4096
#define NSAMP 256
#define NTOT  (NRAYS*NSAMP)
#define STRIDE (NTOT + 128)
#define RES   128
#define RES3  (RES*RES*RES)
#define T0    0.2f
#define DT    (2.8f/255.0f)
#define ACT_SHIFT (-4.595119850134589f)

// ---------------- scratch ----------------------------------------------------
__device__ float    g_alpha[NTOT];
__device__ float    g_rgb[3*NTOT];      // only in-box entries written; rest stay 0
__device__ float    g_nrm[3*NTOT];
__device__ uint32_t g_feat[64*STRIDE];  // (hi fp16 | lo fp16 << 16), column-major; rows 54-63 stay 0
__device__ int      g_sidx[STRIDE];
__device__ int      g_count;

// ---------------- helpers ----------------------------------------------------
__device__ __forceinline__ void split_h(float v, unsigned short &h, unsigned short &l){
    __half hb = __float2half_rn(v);
    float hv = __half2float(hb);
    __half lb = __float2half_rn(v - hv);
    h = __half_as_ushort(hb);
    l = __half_as_ushort(lb);
}
__device__ __forceinline__ uint32_t pack16(unsigned short lo, unsigned short hi){
    return (uint32_t)lo | ((uint32_t)hi << 16);
}
__device__ __forceinline__ void mma_fp16(float* d, uint32_t a0, uint32_t a1,
                                         uint32_t a2, uint32_t a3,
                                         uint32_t b0, uint32_t b1){
    asm volatile(
        "mma.sync.aligned.m16n8k16.row.col.f32.f16.f16.f32 "
        "{%0,%1,%2,%3}, {%4,%5,%6,%7}, {%8,%9}, {%0,%1,%2,%3};"
        : "+f"(d[0]), "+f"(d[1]), "+f"(d[2]), "+f"(d[3])
        : "r"(a0), "r"(a1), "r"(a2), "r"(a3), "r"(b0), "r"(b1));
}

// ---------------- kernel 1: featurize + compact ------------------------------
__device__ __forceinline__ void put_feat(int k, int pos, float v){
    unsigned short h, l;
    split_h(v, h, l);
    g_feat[k*STRIDE + pos] = pack16(h, l);
}

__global__ __launch_bounds__(128) void k_feat(
    const float* __restrict__ rays_o, const float* __restrict__ rays_d,
    const float* __restrict__ viewdirs,
    const float* __restrict__ lat_grid, const float* __restrict__ nrm_grid)
{
    int idx  = blockIdx.x * 128 + threadIdx.x;
    int r    = idx >> 8, s = idx & 255;
    int lane = threadIdx.x & 31;

    float ox = rays_o[r*3], oy = rays_o[r*3+1], oz = rays_o[r*3+2];
    float dx = rays_d[r*3], dy = rays_d[r*3+1], dz = rays_d[r*3+2];
    float dinv = rsqrtf(dx*dx + dy*dy + dz*dz);
    dx *= dinv; dy *= dinv; dz *= dinv;

    float t  = T0 + (float)s * DT;
    float px = ox + dx*t, py = oy + dy*t, pz = oz + dz*t;

    bool inb = (px >= -1.0f) & (px <= 1.0f) & (py >= -1.0f) & (py <= 1.0f)
             & (pz >= -1.0f) & (pz <= 1.0f);

    unsigned mask = __ballot_sync(0xffffffffu, inb);
    int base = 0;
    if (mask){
        if (lane == 0) base = atomicAdd(&g_count, __popc(mask));
        base = __shfl_sync(0xffffffffu, base, 0);
    }
    if (!inb){ g_alpha[idx] = 0.0f; return; }
    int pos = base + __popc(mask & ((1u << lane) - 1u));
    g_sidx[pos] = idx;

    float ux = fminf(fmaxf((px + 1.0f) * 0.5f, 0.0f), 1.0f) * 127.0f;
    float uy = fminf(fmaxf((py + 1.0f) * 0.5f, 0.0f), 1.0f) * 127.0f;
    float uz = fminf(fmaxf((pz + 1.0f) * 0.5f, 0.0f), 1.0f) * 127.0f;
    int x0 = min((int)floorf(ux), 126);
    int y0 = min((int)floorf(uy), 126);
    int z0 = min((int)floorf(uz), 126);
    float fx = ux - (float)x0, fy = uy - (float)y0, fz = uz - (float)z0;
    float gx = 1.0f - fx, gy = 1.0f - fy, gz = 1.0f - fz;
    float w000 = gx*gy*gz, w100 = fx*gy*gz, w010 = gx*fy*gz, w001 = gx*gy*fz;
    float w110 = fx*fy*gz, w101 = fx*gy*fz, w011 = gx*fy*fz, w111 = fx*fy*fz;

    int o000 = (x0*RES + y0)*RES + z0;
    int o100 = o000 + RES*RES, o010 = o000 + RES, o001 = o000 + 1;
    int o110 = o100 + RES,     o101 = o100 + 1,   o011 = o010 + 1;
    int o111 = o110 + 1;

    float lat[16];
    #pragma unroll
    for (int c = 0; c < 16; c++){
        const float *g = lat_grid + c*RES3;
        lat[c] = w000*__ldg(g+o000) + w100*__ldg(g+o100) + w010*__ldg(g+o010)
               + w001*__ldg(g+o001) + w110*__ldg(g+o110) + w101*__ldg(g+o101)
               + w011*__ldg(g+o011) + w111*__ldg(g+o111);
    }
    float nv[3];
    #pragma unroll
    for (int c = 0; c < 3; c++){
        const float *g = nrm_grid + c*RES3;
        nv[c] = w000*__ldg(g+o000) + w100*__ldg(g+o100) + w010*__ldg(g+o010)
              + w001*__ldg(g+o001) + w110*__ldg(g+o110) + w101*__ldg(g+o101)
              + w011*__ldg(g+o011) + w111*__ldg(g+o111);
    }
    float nx = nv[0], ny = nv[1], nz = nv[2];
    float nl = sqrtf(nx*nx + ny*ny + nz*nz);
    float ninv = 1.0f / fmaxf(nl, 1e-12f);
    nx *= ninv; ny *= ninv; nz *= ninv;

    float d0 = lat[0] + ACT_SHIFT;
    float sp = fmaxf(d0, 0.0f) + log1pf(__expf(-fabsf(d0)));
    g_alpha[idx] = 1.0f - __expf(-sp * 0.5f);
    g_nrm[idx] = nx; g_nrm[NTOT+idx] = ny; g_nrm[2*NTOT+idx] = nz;

    float vx = viewdirs[r*3], vy = viewdirs[r*3+1], vz = viewdirs[r*3+2];
    float vinv = rsqrtf(vx*vx + vy*vy + vz*vz);
    vx *= vinv; vy *= vinv; vz *= vinv;
    float dot = -(vx*nx + vy*ny + vz*nz);
    float rdx = 2.0f*dot*nx + vx, rdy = 2.0f*dot*ny + vy, rdz = 2.0f*dot*nz + vz;

    #pragma unroll
    for (int c = 0; c < 15; c++) put_feat(c, pos, lat[c+1]);
    put_feat(15, pos, rdx); put_feat(16, pos, rdy); put_feat(17, pos, rdz);
    float f = 1.0f;
    #pragma unroll
    for (int k = 0; k < 6; k++){
        float sx, cx, sy, cy, sz, cz;
        __sincosf(f*rdx, &sx, &cx);
        __sincosf(f*rdy, &sy, &cy);
        __sincosf(f*rdz, &sz, &cz);
        put_feat(18+3*k,   pos, sx); put_feat(18+3*k+1, pos, sy); put_feat(18+3*k+2, pos, sz);
        put_feat(36+3*k,   pos, cx); put_feat(36+3*k+1, pos, cy); put_feat(36+3*k+2, pos, cz);
        f *= 2.0f;
    }
}

// ---------------- kernel 2: register-chained HMMA MLP ------------------------
// SMEM layout (bytes):
#define BH_OFF   0          // B hi frags: [L][n][ks][lane] * 8B = 3*8*4*32*8 = 24576
#define BL_OFF   24576      // B lo frags: 24576
#define A_HI     49152      // 128 rows * 144B = 18432
#define A_LO     67584      // 18432
#define BIAS_OFF 86016      // b0,b1,b2 : 3*256
#define W3B_OFF  86784      // 192*4
#define B3_OFF   87552      // 16
#define SMEM_SZ  87568

__global__ __launch_bounds__(128) void k_mlp(
    const float* __restrict__ W0, const float* __restrict__ b0,
    const float* __restrict__ W1, const float* __restrict__ b1,
    const float* __restrict__ W2, const float* __restrict__ b2,
    const float* __restrict__ W3, const float* __restrict__ b3)
{
    extern __shared__ __align__(16) char smem[];
    int tid = threadIdx.x, wid = tid >> 5, lane = tid & 31;
    int gq = lane >> 2, t = lane & 3;
    int wbase = wid * 32;

    // ---- B fragments, fragment-major, hi/lo fp16 split ----
    for (int i = tid; i < 3072; i += 128){
        int ln = i & 31, ks = (i >> 5) & 3, n = (i >> 7) & 7, L = i >> 10;
        int g = ln >> 2, tt = ln & 3;
        int col = 8*n + g;
        int k0 = 16*ks + 2*tt;
        float w[4];
        #pragma unroll
        for (int j = 0; j < 4; j++){
            int kk = k0 + (j >> 1)*8 + (j & 1);
            float v;
            if (L == 0)      v = (kk < 54) ? __ldg(W0 + kk*64 + col) : 0.0f;
            else if (L == 1) v = __ldg(W1 + kk*64 + col);
            else             v = __ldg(W2 + kk*64 + col);
            w[j] = v;
        }
        unsigned short h0,l0,h1,l1,h2,l2,h3,l3;
        split_h(w[0],h0,l0); split_h(w[1],h1,l1);
        split_h(w[2],h2,l2); split_h(w[3],h3,l3);
        uint2 hi = make_uint2(pack16(h0,h1), pack16(h2,h3));
        uint2 lo = make_uint2(pack16(l0,l1), pack16(l2,l3));
        *(uint2*)(smem + BH_OFF + i*8) = hi;
        *(uint2*)(smem + BL_OFF + i*8) = lo;
    }
    for (int i = tid; i < 192; i += 128) *(float*)(smem + W3B_OFF + 4*i) = W3[i];
    if (tid < 64){
        *(float*)(smem + BIAS_OFF        + 4*tid) = b0[tid];
        *(float*)(smem + BIAS_OFF + 256  + 4*tid) = b1[tid];
        *(float*)(smem + BIAS_OFF + 512  + 4*tid) = b2[tid];
    }
    if (tid < 3) *(float*)(smem + B3_OFF + 4*tid) = b3[tid];
    __syncthreads();

    int cnt    = g_count;
    int ntiles = (cnt + 127) >> 7;

    for (int tile = blockIdx.x; tile < ntiles; tile += gridDim.x){
        int tbase = tile << 7;

        // ---- A tile -> smem planes (layer-0 only) ----
        for (int i = tid; i < 8192; i += 128){
            int rr = i & 127, k = i >> 7;
            uint32_t v = g_feat[k*STRIDE + tbase + rr];
            int off = rr*144 + 2*k;
            *(unsigned short*)(smem + A_HI + off) = (unsigned short)(v & 0xffffu);
            *(unsigned short*)(smem + A_LO + off) = (unsigned short)(v >> 16);
        }
        __syncthreads();

        // ---- load layer-0 A fragments ----
        uint32_t ah[2][4][4], al[2][4][4];
        #pragma unroll
        for (int m = 0; m < 2; m++){
            int R = wbase + 16*m + gq;
            #pragma unroll
            for (int ks = 0; ks < 4; ks++){
                int base = R*144 + 32*ks + 4*t;
                ah[m][ks][0] = *(uint32_t*)(smem + A_HI + base);
                ah[m][ks][1] = *(uint32_t*)(smem + A_HI + base + 8*144);
                ah[m][ks][2] = *(uint32_t*)(smem + A_HI + base + 16);
                ah[m][ks][3] = *(uint32_t*)(smem + A_HI + base + 8*144 + 16);
                al[m][ks][0] = *(uint32_t*)(smem + A_LO + base);
                al[m][ks][1] = *(uint32_t*)(smem + A_LO + base + 8*144);
                al[m][ks][2] = *(uint32_t*)(smem + A_LO + base + 16);
                al[m][ks][3] = *(uint32_t*)(smem + A_LO + base + 8*144 + 16);
            }
        }
        __syncthreads();   // frag loads done before next tile's refill

        float rgbq[4][3];

        #pragma unroll 1
        for (int L = 0; L < 3; L++){
            float acc[2][8][4];
            #pragma unroll
            for (int m = 0; m < 2; m++)
                #pragma unroll
                for (int n = 0; n < 8; n++)
                    #pragma unroll
                    for (int j = 0; j < 4; j++) acc[m][n][j] = 0.0f;

            // passes Ah*Bh and Al*Bh (Bh reused)
            #pragma unroll
            for (int ks = 0; ks < 4; ks++){
                uint2 B[8];
                #pragma unroll
                for (int n = 0; n < 8; n++)
                    B[n] = *(uint2*)(smem + BH_OFF + ((((L*8 + n)*4 + ks)*32 + lane)*8));
                #pragma unroll
                for (int n = 0; n < 8; n++){
                    mma_fp16(acc[0][n], ah[0][ks][0], ah[0][ks][1], ah[0][ks][2], ah[0][ks][3], B[n].x, B[n].y);
                    mma_fp16(acc[1][n], ah[1][ks][0], ah[1][ks][1], ah[1][ks][2], ah[1][ks][3], B[n].x, B[n].y);
                }
                #pragma unroll
                for (int n = 0; n < 8; n++){
                    mma_fp16(acc[0][n], al[0][ks][0], al[0][ks][1], al[0][ks][2], al[0][ks][3], B[n].x, B[n].y);
                    mma_fp16(acc[1][n], al[1][ks][0], al[1][ks][1], al[1][ks][2], al[1][ks][3], B[n].x, B[n].y);
                }
            }
            // pass Ah*Bl
            #pragma unroll
            for (int ks = 0; ks < 4; ks++){
                uint2 B[8];
                #pragma unroll
                for (int n = 0; n < 8; n++)
                    B[n] = *(uint2*)(smem + BL_OFF + ((((L*8 + n)*4 + ks)*32 + lane)*8));
                #pragma unroll
                for (int n = 0; n < 8; n++){
                    mma_fp16(acc[0][n], ah[0][ks][0], ah[0][ks][1], ah[0][ks][2], ah[0][ks][3], B[n].x, B[n].y);
                    mma_fp16(acc[1][n], ah[1][ks][0], ah[1][ks][1], ah[1][ks][2], ah[1][ks][3], B[n].x, B[n].y);
                }
            }

            if (L < 2){
                // bias + relu + fp16 split, repack into next-layer A fragments
                #pragma unroll
                for (int m = 0; m < 2; m++)
                    #pragma unroll
                    for (int n = 0; n < 8; n++){
                        float2 bb = *(float2*)(smem + BIAS_OFF + L*256 + (8*n + 2*t)*4);
                        float v0 = fmaxf(acc[m][n][0] + bb.x, 0.0f);
                        float v1 = fmaxf(acc[m][n][1] + bb.y, 0.0f);
                        float v2 = fmaxf(acc[m][n][2] + bb.x, 0.0f);
                        float v3 = fmaxf(acc[m][n][3] + bb.y, 0.0f);
                        unsigned short h0,l0,h1,l1,h2,l2,h3,l3;
                        split_h(v0,h0,l0); split_h(v1,h1,l1);
                        split_h(v2,h2,l2); split_h(v3,h3,l3);
                        int ks = n >> 1, w = (n & 1)*2;
                        ah[m][ks][w]   = pack16(h0,h1);
                        al[m][ks][w]   = pack16(l0,l1);
                        ah[m][ks][w+1] = pack16(h2,h3);
                        al[m][ks][w+1] = pack16(l2,l3);
                    }
            } else {
                const float* w3 = (const float*)(smem + W3B_OFF);
                #pragma unroll
                for (int sl = 0; sl < 4; sl++){ rgbq[sl][0]=0.f; rgbq[sl][1]=0.f; rgbq[sl][2]=0.f; }
                #pragma unroll
                for (int m = 0; m < 2; m++)
                    #pragma unroll
                    for (int n = 0; n < 8; n++){
                        int col0 = n*8 + 2*t;
                        float2 bb = *(float2*)(smem + BIAS_OFF + 512 + col0*4);
                        float v0 = fmaxf(acc[m][n][0] + bb.x, 0.0f);
                        float v1 = fmaxf(acc[m][n][1] + bb.y, 0.0f);
                        float v2 = fmaxf(acc[m][n][2] + bb.x, 0.0f);
                        float v3 = fmaxf(acc[m][n][3] + bb.y, 0.0f);
                        #pragma unroll
                        for (int c = 0; c < 3; c++){
                            rgbq[2*m  ][c] += v0*w3[col0*3+c] + v1*w3[(col0+1)*3+c];
                            rgbq[2*m+1][c] += v2*w3[col0*3+c] + v3*w3[(col0+1)*3+c];
                        }
                    }
            }
        }

        // reduce layer-3 partials across the 4 lanes sharing gq
        #pragma unroll
        for (int sl = 0; sl < 4; sl++)
            #pragma unroll
            for (int c = 0; c < 3; c++){
                float v = rgbq[sl][c];
                v += __shfl_xor_sync(0xffffffffu, v, 1);
                v += __shfl_xor_sync(0xffffffffu, v, 2);
                rgbq[sl][c] = v;
            }
        if (t == 0){
            const float* bb3 = (const float*)(smem + B3_OFF);
            #pragma unroll
            for (int sl = 0; sl < 4; sl++){
                int m = sl >> 1, h = sl & 1;
                int gi = tbase + wbase + m*16 + gq + 8*h;
                if (gi < cnt){
                    int sidx = g_sidx[gi];
                    g_rgb[sidx]        = 1.0f/(1.0f + __expf(-(rgbq[sl][0] + bb3[0])));
                    g_rgb[NTOT+sidx]   = 1.0f/(1.0f + __expf(-(rgbq[sl][1] + bb3[1])));
                    g_rgb[2*NTOT+sidx] = 1.0f/(1.0f + __expf(-(rgbq[sl][2] + bb3[2])));
                }
            }
        }
    }
}

// ---------------- kernel 3: warp-per-ray composite ---------------------------
__global__ __launch_bounds__(256) void k_perray(float* __restrict__ out)
{
    if (blockIdx.x == 0 && threadIdx.x == 0) g_count = 0;  // reset for next replay
    int r    = (blockIdx.x * 256 + threadIdx.x) >> 5;
    int lane = threadIdx.x & 31;
    if (r >= NRAYS) return;

    float *o_rgb   = out;
    float *o_depth = out + 12288;
    float *o_disp  = out + 16384;
    float *o_acc   = out + 20480;
    float *o_nrm   = out + 24576;
    float *o_w     = out + 36864;
    float *o_ai    = out + 1085440;

    float P = 1.0f;
    float sr0=0.f, sr1=0.f, sr2=0.f, sd=0.f, sa=0.f, sn0=0.f, sn1=0.f, sn2=0.f;

    #pragma unroll 1
    for (int c = 0; c < 8; c++){
        int s   = c*32 + lane;
        int idx = (r << 8) + s;
        float alp = g_alpha[idx];
        float v   = fmaxf(1.0f - alp, 1e-10f);
        #pragma unroll
        for (int off = 1; off < 32; off <<= 1){
            float o = __shfl_up_sync(0xffffffffu, v, off);
            if (lane >= off) v *= o;
        }
        float pv   = __shfl_up_sync(0xffffffffu, v, 1);
        float excl = lane ? P * pv : P;
        float incl = P * v;
        float w    = alp * excl;
        o_w[idx]            = w;
        o_ai[r*257 + 1 + s] = incl;
        float t = T0 + (float)s * DT;
        sd += w * t; sa += w;
        sr0 += w * g_rgb[idx]; sr1 += w * g_rgb[NTOT+idx]; sr2 += w * g_rgb[2*NTOT+idx];
        sn0 += w * g_nrm[idx]; sn1 += w * g_nrm[NTOT+idx]; sn2 += w * g_nrm[2*NTOT+idx];
        P = __shfl_sync(0xffffffffu, incl, 31);
    }
    #pragma unroll
    for (int off = 16; off; off >>= 1){
        sr0 += __shfl_xor_sync(0xffffffffu, sr0, off);
        sr1 += __shfl_xor_sync(0xffffffffu, sr1, off);
        sr2 += __shfl_xor_sync(0xffffffffu, sr2, off);
        sd  += __shfl_xor_sync(0xffffffffu, sd,  off);
        sa  += __shfl_xor_sync(0xffffffffu, sa,  off);
        sn0 += __shfl_xor_sync(0xffffffffu, sn0, off);
        sn1 += __shfl_xor_sync(0xffffffffu, sn1, off);
        sn2 += __shfl_xor_sync(0xffffffffu, sn2, off);
    }
    if (lane == 0){
        o_rgb[r*3]   = sr0 + P;
        o_rgb[r*3+1] = sr1 + P;
        o_rgb[r*3+2] = sr2 + P;
        float dm = sd + P * 3.0f;
        o_depth[r] = dm;
        o_disp[r]  = 1.0f / dm;
        o_acc[r]   = sa;
        o_nrm[r*3]   = sn0;
        o_nrm[r*3+1] = sn1;
        o_nrm[r*3+2] = sn2;
        o_ai[r*257]  = 1.0f;
    }
}

extern "C" void kernel_launch(void* const* d_in, const int* in_sizes, int n_in,
                              void* d_out, int out_size)
{
    const float* rays_o   = (const float*)d_in[0];
    const float* rays_d   = (const float*)d_in[1];
    const float* viewdirs = (const float*)d_in[2];
    const float* lat_grid = (const float*)d_in[3];
    const float* nrm_grid = (const float*)d_in[4];
    const float* W0 = (const float*)d_in[5];
    const float* b0 = (const float*)d_in[6];
    const float* W1 = (const float*)d_in[7];
    const float* b1 = (const float*)d_in[8];
    const float* W2 = (const float*)d_in[9];
    const float* b2 = (const float*)d_in[10];
    const float* W3 = (const float*)d_in[11];
    const float* b3 = (const float*)d_in[12];

    static int smem_set = 0;
    if (!smem_set){
        cudaFuncSetAttribute(k_mlp, cudaFuncAttributeMaxDynamicSharedMemorySize, SMEM_SZ);
        smem_set = 1;
    }

    k_feat<<<NTOT/128, 128>>>(rays_o, rays_d, viewdirs, lat_grid, nrm_grid);
    k_mlp<<<296, 128, SMEM_SZ>>>(W0, b0, W1, b1, W2, b2, W3, b3);
    k_perray<<<NRAYS*32/256, 256>>>((float*)d_out);
}

// round 5
// speedup vs baseline: 4.9033x; 2.0886x over previous
#include <cuda_runtime.h>
#include <cuda_fp16.h>
#include <math.h>
#include <stdint.h>

#define NRAYS 4096
#define NSAMP 256
#define NTOT  (NRAYS*NSAMP)
#define STRIDE (NTOT + 128)
#define RES   128
#define RES3  (RES*RES*RES)
#define T0    0.2f
#define DT    (2.8f/255.0f)
#define ACT_SHIFT (-4.595119850134589f)

// ---------------- scratch ----------------------------------------------------
__device__ float    g_alpha[NTOT];
__device__ float    g_rgb[3*NTOT];
__device__ float    g_nrm[3*NTOT];
__device__ uint4    g_lat4[2*RES3];     // 16 fp16 latent channels per voxel
__device__ uint2    g_nrm2[RES3];       // nx,ny,nz fp16 + pad
__device__ uint32_t g_feat2[32*STRIDE]; // fp16 feature pairs, pair-major
__device__ int      g_sidx[STRIDE];
__device__ int      g_count;

// ---------------- helpers ----------------------------------------------------
__device__ __forceinline__ uint32_t pack16(unsigned short lo, unsigned short hi){
    return (uint32_t)lo | ((uint32_t)hi << 16);
}
__device__ __forceinline__ unsigned short f2h(float v){
    return __half_as_ushort(__float2half_rn(v));
}
__device__ __forceinline__ float2 h2f(uint32_t u){
    __half2 h = *reinterpret_cast<__half2*>(&u);
    return __half22float2(h);
}
__device__ __forceinline__ void mma_fp16(float* d, uint32_t a0, uint32_t a1,
                                         uint32_t a2, uint32_t a3,
                                         uint32_t b0, uint32_t b1){
    asm volatile(
        "mma.sync.aligned.m16n8k16.row.col.f32.f16.f16.f32 "
        "{%0,%1,%2,%3}, {%4,%5,%6,%7}, {%8,%9}, {%0,%1,%2,%3};"
        : "+f"(d[0]), "+f"(d[1]), "+f"(d[2]), "+f"(d[3])
        : "r"(a0), "r"(a1), "r"(a2), "r"(a3), "r"(b0), "r"(b1));
}

// ---------------- kernel 0: grid transpose to voxel-interleaved fp16 ---------
__global__ __launch_bounds__(256) void k_xpose(
    const float* __restrict__ lat, const float* __restrict__ nrm)
{
    int v = blockIdx.x * 256 + threadIdx.x;
    unsigned short h[16];
    #pragma unroll
    for (int c = 0; c < 16; c++) h[c] = f2h(__ldg(lat + c*RES3 + v));
    uint4 a, b;
    a.x = pack16(h[0],h[1]);   a.y = pack16(h[2],h[3]);
    a.z = pack16(h[4],h[5]);   a.w = pack16(h[6],h[7]);
    b.x = pack16(h[8],h[9]);   b.y = pack16(h[10],h[11]);
    b.z = pack16(h[12],h[13]); b.w = pack16(h[14],h[15]);
    g_lat4[2*v]   = a;
    g_lat4[2*v+1] = b;
    uint2 q;
    q.x = pack16(f2h(__ldg(nrm + v)), f2h(__ldg(nrm + RES3 + v)));
    q.y = pack16(f2h(__ldg(nrm + 2*RES3 + v)), 0);
    g_nrm2[v] = q;
}

// ---------------- kernel 1: featurize + compact ------------------------------
__global__ __launch_bounds__(128) void k_feat(
    const float* __restrict__ rays_o, const float* __restrict__ rays_d,
    const float* __restrict__ viewdirs)
{
    int idx  = blockIdx.x * 128 + threadIdx.x;
    int r    = idx >> 8, s = idx & 255;
    int lane = threadIdx.x & 31;

    float ox = rays_o[r*3], oy = rays_o[r*3+1], oz = rays_o[r*3+2];
    float dx = rays_d[r*3], dy = rays_d[r*3+1], dz = rays_d[r*3+2];
    float dinv = rsqrtf(dx*dx + dy*dy + dz*dz);
    dx *= dinv; dy *= dinv; dz *= dinv;

    float t  = T0 + (float)s * DT;
    float px = ox + dx*t, py = oy + dy*t, pz = oz + dz*t;

    bool inb = (px >= -1.0f) & (px <= 1.0f) & (py >= -1.0f) & (py <= 1.0f)
             & (pz >= -1.0f) & (pz <= 1.0f);

    unsigned mask = __ballot_sync(0xffffffffu, inb);
    int base = 0;
    if (mask){
        if (lane == 0) base = atomicAdd(&g_count, __popc(mask));
        base = __shfl_sync(0xffffffffu, base, 0);
    }
    if (!inb){ g_alpha[idx] = 0.0f; return; }
    int pos = base + __popc(mask & ((1u << lane) - 1u));
    g_sidx[pos] = idx;

    float ux = fminf(fmaxf((px + 1.0f) * 0.5f, 0.0f), 1.0f) * 127.0f;
    float uy = fminf(fmaxf((py + 1.0f) * 0.5f, 0.0f), 1.0f) * 127.0f;
    float uz = fminf(fmaxf((pz + 1.0f) * 0.5f, 0.0f), 1.0f) * 127.0f;
    int x0 = min((int)floorf(ux), 126);
    int y0 = min((int)floorf(uy), 126);
    int z0 = min((int)floorf(uz), 126);
    float fx = ux - (float)x0, fy = uy - (float)y0, fz = uz - (float)z0;
    float gx = 1.0f - fx, gy = 1.0f - fy, gz = 1.0f - fz;

    int o000 = (x0*RES + y0)*RES + z0;
    int offs[8] = { o000, o000+1, o000+RES, o000+RES+1,
                    o000+RES*RES, o000+RES*RES+1, o000+RES*RES+RES, o000+RES*RES+RES+1 };
    float ws[8] = { gx*gy*gz, gx*gy*fz, gx*fy*gz, gx*fy*fz,
                    fx*gy*gz, fx*gy*fz, fx*fy*gz, fx*fy*fz };

    float L[16]; float N3[3];
    #pragma unroll
    for (int c = 0; c < 16; c++) L[c] = 0.0f;
    N3[0] = N3[1] = N3[2] = 0.0f;

    #pragma unroll
    for (int c = 0; c < 8; c++){
        int o = offs[c];
        float w = ws[c];
        uint4 pa = __ldg(&g_lat4[2*o]);
        uint4 pb = __ldg(&g_lat4[2*o+1]);
        uint2 pn = __ldg(&g_nrm2[o]);
        float2 f;
        f = h2f(pa.x); L[0]  += w*f.x; L[1]  += w*f.y;
        f = h2f(pa.y); L[2]  += w*f.x; L[3]  += w*f.y;
        f = h2f(pa.z); L[4]  += w*f.x; L[5]  += w*f.y;
        f = h2f(pa.w); L[6]  += w*f.x; L[7]  += w*f.y;
        f = h2f(pb.x); L[8]  += w*f.x; L[9]  += w*f.y;
        f = h2f(pb.y); L[10] += w*f.x; L[11] += w*f.y;
        f = h2f(pb.z); L[12] += w*f.x; L[13] += w*f.y;
        f = h2f(pb.w); L[14] += w*f.x; L[15] += w*f.y;
        f = h2f(pn.x); N3[0] += w*f.x; N3[1] += w*f.y;
        f = h2f(pn.y); N3[2] += w*f.x;
    }

    float nx = N3[0], ny = N3[1], nz = N3[2];
    float nl = sqrtf(nx*nx + ny*ny + nz*nz);
    float ninv = 1.0f / fmaxf(nl, 1e-12f);
    nx *= ninv; ny *= ninv; nz *= ninv;

    float d0 = L[0] + ACT_SHIFT;
    float sp = fmaxf(d0, 0.0f) + log1pf(__expf(-fabsf(d0)));
    g_alpha[idx] = 1.0f - __expf(-sp * 0.5f);
    g_nrm[idx] = nx; g_nrm[NTOT+idx] = ny; g_nrm[2*NTOT+idx] = nz;

    float vx = viewdirs[r*3], vy = viewdirs[r*3+1], vz = viewdirs[r*3+2];
    float vinv = rsqrtf(vx*vx + vy*vy + vz*vz);
    vx *= vinv; vy *= vinv; vz *= vinv;
    float dot = -(vx*nx + vy*ny + vz*nz);
    float rdx = 2.0f*dot*nx + vx, rdy = 2.0f*dot*ny + vy, rdz = 2.0f*dot*nz + vz;

    float fv[54];
    #pragma unroll
    for (int c = 0; c < 15; c++) fv[c] = L[c+1];
    fv[15] = rdx; fv[16] = rdy; fv[17] = rdz;
    float fq = 1.0f;
    #pragma unroll
    for (int k = 0; k < 6; k++){
        float sx, cx, sy, cy, sz, cz;
        __sincosf(fq*rdx, &sx, &cx);
        __sincosf(fq*rdy, &sy, &cy);
        __sincosf(fq*rdz, &sz, &cz);
        fv[18+3*k] = sx; fv[18+3*k+1] = sy; fv[18+3*k+2] = sz;
        fv[36+3*k] = cx; fv[36+3*k+1] = cy; fv[36+3*k+2] = cz;
        fq *= 2.0f;
    }
    #pragma unroll
    for (int kp = 0; kp < 27; kp++)
        g_feat2[kp*STRIDE + pos] = pack16(f2h(fv[2*kp]), f2h(fv[2*kp+1]));
    #pragma unroll
    for (int kp = 27; kp < 32; kp++)
        g_feat2[kp*STRIDE + pos] = 0;
}

// ---------------- kernel 2: single-pass fp16 HMMA MLP ------------------------
#define BF_OFF   0          // B frags: 3*8*4*32*8 = 24576
#define A_OFF    24576      // 128 rows * 144B = 18432
#define BIAS_OFF 43008      // b0,b1,b2 : 3*256
#define W3B_OFF  43776      // 192*4
#define B3_OFF   44544      // 16
#define SMEM_SZ  44560

__global__ __launch_bounds__(128) void k_mlp(
    const float* __restrict__ W0, const float* __restrict__ b0,
    const float* __restrict__ W1, const float* __restrict__ b1,
    const float* __restrict__ W2, const float* __restrict__ b2,
    const float* __restrict__ W3, const float* __restrict__ b3)
{
    __shared__ __align__(16) char smem[SMEM_SZ];
    int tid = threadIdx.x, wid = tid >> 5, lane = tid & 31;
    int gq = lane >> 2, t = lane & 3;
    int wbase = wid * 32;

    // ---- B fragments (fp16, fragment-major) ----
    for (int i = tid; i < 3072; i += 128){
        int ln = i & 31, ks = (i >> 5) & 3, n = (i >> 7) & 7, L = i >> 10;
        int g = ln >> 2, tt = ln & 3;
        int col = 8*n + g;
        int k0 = 16*ks + 2*tt;
        unsigned short h[4];
        #pragma unroll
        for (int j = 0; j < 4; j++){
            int kk = k0 + (j >> 1)*8 + (j & 1);
            float v;
            if (L == 0)      v = (kk < 54) ? __ldg(W0 + kk*64 + col) : 0.0f;
            else if (L == 1) v = __ldg(W1 + kk*64 + col);
            else             v = __ldg(W2 + kk*64 + col);
            h[j] = f2h(v);
        }
        *(uint2*)(smem + BF_OFF + i*8) = make_uint2(pack16(h[0],h[1]), pack16(h[2],h[3]));
    }
    for (int i = tid; i < 192; i += 128) *(float*)(smem + W3B_OFF + 4*i) = W3[i];
    if (tid < 64){
        *(float*)(smem + BIAS_OFF        + 4*tid) = b0[tid];
        *(float*)(smem + BIAS_OFF + 256  + 4*tid) = b1[tid];
        *(float*)(smem + BIAS_OFF + 512  + 4*tid) = b2[tid];
    }
    if (tid < 3) *(float*)(smem + B3_OFF + 4*tid) = b3[tid];
    __syncthreads();

    int cnt    = g_count;
    int ntiles = (cnt + 127) >> 7;

    for (int tile = blockIdx.x; tile < ntiles; tile += gridDim.x){
        int tbase = tile << 7;

        // A tile: 128 rows x 32 fp16-pairs, row pad to 144B
        #pragma unroll 8
        for (int j = 0; j < 32; j++){
            uint32_t v = g_feat2[j*STRIDE + tbase + tid];
            *(uint32_t*)(smem + A_OFF + tid*144 + j*4) = v;
        }
        __syncthreads();

        uint32_t ah[2][4][4];
        #pragma unroll
        for (int m = 0; m < 2; m++){
            int R = wbase + 16*m + gq;
            #pragma unroll
            for (int ks = 0; ks < 4; ks++){
                int base = A_OFF + R*144 + 32*ks + 4*t;
                ah[m][ks][0] = *(uint32_t*)(smem + base);
                ah[m][ks][1] = *(uint32_t*)(smem + base + 8*144);
                ah[m][ks][2] = *(uint32_t*)(smem + base + 16);
                ah[m][ks][3] = *(uint32_t*)(smem + base + 8*144 + 16);
            }
        }
        __syncthreads();

        float rgbq[4][3];

        #pragma unroll 1
        for (int L = 0; L < 3; L++){
            float acc[2][8][4];
            #pragma unroll
            for (int m = 0; m < 2; m++)
                #pragma unroll
                for (int n = 0; n < 8; n++)
                    #pragma unroll
                    for (int j = 0; j < 4; j++) acc[m][n][j] = 0.0f;

            #pragma unroll
            for (int ks = 0; ks < 4; ks++){
                uint2 B[8];
                #pragma unroll
                for (int n = 0; n < 8; n++)
                    B[n] = *(uint2*)(smem + BF_OFF + ((((L*8 + n)*4 + ks)*32 + lane)*8));
                #pragma unroll
                for (int n = 0; n < 8; n++){
                    mma_fp16(acc[0][n], ah[0][ks][0], ah[0][ks][1], ah[0][ks][2], ah[0][ks][3], B[n].x, B[n].y);
                    mma_fp16(acc[1][n], ah[1][ks][0], ah[1][ks][1], ah[1][ks][2], ah[1][ks][3], B[n].x, B[n].y);
                }
            }

            if (L < 2){
                #pragma unroll
                for (int m = 0; m < 2; m++)
                    #pragma unroll
                    for (int n = 0; n < 8; n++){
                        float2 bb = *(float2*)(smem + BIAS_OFF + L*256 + (8*n + 2*t)*4);
                        float v0 = fmaxf(acc[m][n][0] + bb.x, 0.0f);
                        float v1 = fmaxf(acc[m][n][1] + bb.y, 0.0f);
                        float v2 = fmaxf(acc[m][n][2] + bb.x, 0.0f);
                        float v3 = fmaxf(acc[m][n][3] + bb.y, 0.0f);
                        int ks = n >> 1, w = (n & 1)*2;
                        ah[m][ks][w]   = pack16(f2h(v0), f2h(v1));
                        ah[m][ks][w+1] = pack16(f2h(v2), f2h(v3));
                    }
            } else {
                const float* w3 = (const float*)(smem + W3B_OFF);
                #pragma unroll
                for (int sl = 0; sl < 4; sl++){ rgbq[sl][0]=0.f; rgbq[sl][1]=0.f; rgbq[sl][2]=0.f; }
                #pragma unroll
                for (int m = 0; m < 2; m++)
                    #pragma unroll
                    for (int n = 0; n < 8; n++){
                        int col0 = n*8 + 2*t;
                        float2 bb = *(float2*)(smem + BIAS_OFF + 512 + col0*4);
                        float v0 = fmaxf(acc[m][n][0] + bb.x, 0.0f);
                        float v1 = fmaxf(acc[m][n][1] + bb.y, 0.0f);
                        float v2 = fmaxf(acc[m][n][2] + bb.x, 0.0f);
                        float v3 = fmaxf(acc[m][n][3] + bb.y, 0.0f);
                        #pragma unroll
                        for (int c = 0; c < 3; c++){
                            rgbq[2*m  ][c] += v0*w3[col0*3+c] + v1*w3[(col0+1)*3+c];
                            rgbq[2*m+1][c] += v2*w3[col0*3+c] + v3*w3[(col0+1)*3+c];
                        }
                    }
            }
        }

        #pragma unroll
        for (int sl = 0; sl < 4; sl++)
            #pragma unroll
            for (int c = 0; c < 3; c++){
                float v = rgbq[sl][c];
                v += __shfl_xor_sync(0xffffffffu, v, 1);
                v += __shfl_xor_sync(0xffffffffu, v, 2);
                rgbq[sl][c] = v;
            }
        if (t == 0){
            const float* bb3 = (const float*)(smem + B3_OFF);
            #pragma unroll
            for (int sl = 0; sl < 4; sl++){
                int m = sl >> 1, h = sl & 1;
                int gi = tbase + wbase + m*16 + gq + 8*h;
                if (gi < cnt){
                    int sidx = g_sidx[gi];
                    g_rgb[sidx]        = 1.0f/(1.0f + __expf(-(rgbq[sl][0] + bb3[0])));
                    g_rgb[NTOT+sidx]   = 1.0f/(1.0f + __expf(-(rgbq[sl][1] + bb3[1])));
                    g_rgb[2*NTOT+sidx] = 1.0f/(1.0f + __expf(-(rgbq[sl][2] + bb3[2])));
                }
            }
        }
    }
}

// ---------------- kernel 3: warp-per-ray composite ---------------------------
__global__ __launch_bounds__(256) void k_perray(float* __restrict__ out)
{
    if (blockIdx.x == 0 && threadIdx.x == 0) g_count = 0;  // reset for next replay
    int r    = (blockIdx.x * 256 + threadIdx.x) >> 5;
    int lane = threadIdx.x & 31;
    if (r >= NRAYS) return;

    float *o_rgb   = out;
    float *o_depth = out + 12288;
    float *o_disp  = out + 16384;
    float *o_acc   = out + 20480;
    float *o_nrm   = out + 24576;
    float *o_w     = out + 36864;
    float *o_ai    = out + 1085440;

    float P = 1.0f;
    float sr0=0.f, sr1=0.f, sr2=0.f, sd=0.f, sa=0.f, sn0=0.f, sn1=0.f, sn2=0.f;

    #pragma unroll 1
    for (int c = 0; c < 8; c++){
        int s   = c*32 + lane;
        int idx = (r << 8) + s;
        float alp = g_alpha[idx];
        float v   = fmaxf(1.0f - alp, 1e-10f);
        #pragma unroll
        for (int off = 1; off < 32; off <<= 1){
            float o = __shfl_up_sync(0xffffffffu, v, off);
            if (lane >= off) v *= o;
        }
        float pv   = __shfl_up_sync(0xffffffffu, v, 1);
        float excl = lane ? P * pv : P;
        float incl = P * v;
        float w    = alp * excl;
        o_w[idx]            = w;
        o_ai[r*257 + 1 + s] = incl;
        float t = T0 + (float)s * DT;
        sd += w * t; sa += w;
        sr0 += w * g_rgb[idx]; sr1 += w * g_rgb[NTOT+idx]; sr2 += w * g_rgb[2*NTOT+idx];
        sn0 += w * g_nrm[idx]; sn1 += w * g_nrm[NTOT+idx]; sn2 += w * g_nrm[2*NTOT+idx];
        P = __shfl_sync(0xffffffffu, incl, 31);
    }
    #pragma unroll
    for (int off = 16; off; off >>= 1){
        sr0 += __shfl_xor_sync(0xffffffffu, sr0, off);
        sr1 += __shfl_xor_sync(0xffffffffu, sr1, off);
        sr2 += __shfl_xor_sync(0xffffffffu, sr2, off);
        sd  += __shfl_xor_sync(0xffffffffu, sd,  off);
        sa  += __shfl_xor_sync(0xffffffffu, sa,  off);
        sn0 += __shfl_xor_sync(0xffffffffu, sn0, off);
        sn1 += __shfl_xor_sync(0xffffffffu, sn1, off);
        sn2 += __shfl_xor_sync(0xffffffffu, sn2, off);
    }
    if (lane == 0){
        o_rgb[r*3]   = sr0 + P;
        o_rgb[r*3+1] = sr1 + P;
        o_rgb[r*3+2] = sr2 + P;
        float dm = sd + P * 3.0f;
        o_depth[r] = dm;
        o_disp[r]  = 1.0f / dm;
        o_acc[r]   = sa;
        o_nrm[r*3]   = sn0;
        o_nrm[r*3+1] = sn1;
        o_nrm[r*3+2] = sn2;
        o_ai[r*257]  = 1.0f;
    }
}

extern "C" void kernel_launch(void* const* d_in, const int* in_sizes, int n_in,
                              void* d_out, int out_size)
{
    const float* rays_o   = (const float*)d_in[0];
    const float* rays_d   = (const float*)d_in[1];
    const float* viewdirs = (const float*)d_in[2];
    const float* lat_grid = (const float*)d_in[3];
    const float* nrm_grid = (const float*)d_in[4];
    const float* W0 = (const float*)d_in[5];
    const float* b0 = (const float*)d_in[6];
    const float* W1 = (const float*)d_in[7];
    const float* b1 = (const float*)d_in[8];
    const float* W2 = (const float*)d_in[9];
    const float* b2 = (const float*)d_in[10];
    const float* W3 = (const float*)d_in[11];
    const float* b3 = (const float*)d_in[12];

    k_xpose<<<RES3/256, 256>>>(lat_grid, nrm_grid);
    k_feat<<<NTOT/128, 128>>>(rays_o, rays_d, viewdirs);
    k_mlp<<<592, 128>>>(W0, b0, W1, b1, W2, b2, W3, b3);
    k_perray<<<NRAYS*32/256, 256>>>((float*)d_out);
}

// round 6
// speedup vs baseline: 5.1186x; 1.0439x over previous
#include <cuda_runtime.h>
#include <cuda_fp16.h>
#include <math.h>
#include <stdint.h>

#define NRAYS 4096
#define NSAMP 256
#define NTOT  (NRAYS*NSAMP)
#define STRIDE (NTOT + 128)
#define RES   128
#define RES3  (RES*RES*RES)
#define T0    0.2f
#define DT    (2.8f/255.0f)
#define ACT_SHIFT (-4.595119850134589f)

// ---------------- scratch ----------------------------------------------------
__device__ float    g_alpha[NTOT];
__device__ float    g_rgb[3*NTOT];
__device__ float    g_nrm[3*NTOT];
__device__ uint4    g_lat4[2*RES3];     // 16 fp16 latent channels per voxel
__device__ uint2    g_nrm2[RES3];       // nx,ny,nz fp16 + pad
__device__ uint32_t g_feat2[32*STRIDE]; // fp16 feature pairs, pair-major
__device__ int      g_sidx[STRIDE];
__device__ int      g_count;

// ---------------- helpers ----------------------------------------------------
__device__ __forceinline__ uint32_t pack16(unsigned short lo, unsigned short hi){
    return (uint32_t)lo | ((uint32_t)hi << 16);
}
__device__ __forceinline__ unsigned short f2h(float v){
    return __half_as_ushort(__float2half_rn(v));
}
__device__ __forceinline__ float2 h2f(uint32_t u){
    __half2 h = *reinterpret_cast<__half2*>(&u);
    return __half22float2(h);
}
__device__ __forceinline__ void mma_fp16(float* d, uint32_t a0, uint32_t a1,
                                         uint32_t a2, uint32_t a3,
                                         uint32_t b0, uint32_t b1){
    asm volatile(
        "mma.sync.aligned.m16n8k16.row.col.f32.f16.f16.f32 "
        "{%0,%1,%2,%3}, {%4,%5,%6,%7}, {%8,%9}, {%0,%1,%2,%3};"
        : "+f"(d[0]), "+f"(d[1]), "+f"(d[2]), "+f"(d[3])
        : "r"(a0), "r"(a1), "r"(a2), "r"(a3), "r"(b0), "r"(b1));
}

// ---------------- kernel 0: grid transpose (2 voxels/thread, float2 reads) ---
__global__ __launch_bounds__(256) void k_xpose(
    const float* __restrict__ lat, const float* __restrict__ nrm)
{
    int v2 = blockIdx.x * 256 + threadIdx.x;   // voxel pair index
    unsigned short ha[16], hb[16];
    #pragma unroll
    for (int c = 0; c < 16; c++){
        float2 f = __ldg((const float2*)(lat + c*RES3) + v2);
        ha[c] = f2h(f.x); hb[c] = f2h(f.y);
    }
    uint4 w0, w1, w2, w3;
    w0.x = pack16(ha[0],ha[1]);   w0.y = pack16(ha[2],ha[3]);
    w0.z = pack16(ha[4],ha[5]);   w0.w = pack16(ha[6],ha[7]);
    w1.x = pack16(ha[8],ha[9]);   w1.y = pack16(ha[10],ha[11]);
    w1.z = pack16(ha[12],ha[13]); w1.w = pack16(ha[14],ha[15]);
    w2.x = pack16(hb[0],hb[1]);   w2.y = pack16(hb[2],hb[3]);
    w2.z = pack16(hb[4],hb[5]);   w2.w = pack16(hb[6],hb[7]);
    w3.x = pack16(hb[8],hb[9]);   w3.y = pack16(hb[10],hb[11]);
    w3.z = pack16(hb[12],hb[13]); w3.w = pack16(hb[14],hb[15]);
    g_lat4[4*v2]   = w0;
    g_lat4[4*v2+1] = w1;
    g_lat4[4*v2+2] = w2;
    g_lat4[4*v2+3] = w3;
    float2 n0 = __ldg((const float2*)(nrm)            + v2);
    float2 n1 = __ldg((const float2*)(nrm +   RES3)   + v2);
    float2 n2 = __ldg((const float2*)(nrm + 2*RES3)   + v2);
    uint4 nq;
    nq.x = pack16(f2h(n0.x), f2h(n1.x));
    nq.y = pack16(f2h(n2.x), 0);
    nq.z = pack16(f2h(n0.y), f2h(n1.y));
    nq.w = pack16(f2h(n2.y), 0);
    ((uint4*)g_nrm2)[v2] = nq;
}

// ---------------- kernel 1: featurize + compact ------------------------------
__global__ __launch_bounds__(128) void k_feat(
    const float* __restrict__ rays_o, const float* __restrict__ rays_d,
    const float* __restrict__ viewdirs)
{
    int idx  = blockIdx.x * 128 + threadIdx.x;
    int r    = idx >> 8, s = idx & 255;
    int lane = threadIdx.x & 31;

    float ox = rays_o[r*3], oy = rays_o[r*3+1], oz = rays_o[r*3+2];
    float dx = rays_d[r*3], dy = rays_d[r*3+1], dz = rays_d[r*3+2];
    float dinv = rsqrtf(dx*dx + dy*dy + dz*dz);
    dx *= dinv; dy *= dinv; dz *= dinv;

    float t  = T0 + (float)s * DT;
    float px = ox + dx*t, py = oy + dy*t, pz = oz + dz*t;

    bool inb = (px >= -1.0f) & (px <= 1.0f) & (py >= -1.0f) & (py <= 1.0f)
             & (pz >= -1.0f) & (pz <= 1.0f);

    unsigned mask = __ballot_sync(0xffffffffu, inb);
    int base = 0;
    if (mask){
        if (lane == 0) base = atomicAdd(&g_count, __popc(mask));
        base = __shfl_sync(0xffffffffu, base, 0);
    }
    if (!inb){ g_alpha[idx] = 0.0f; return; }
    int pos = base + __popc(mask & ((1u << lane) - 1u));
    g_sidx[pos] = idx;

    float ux = fminf(fmaxf((px + 1.0f) * 0.5f, 0.0f), 1.0f) * 127.0f;
    float uy = fminf(fmaxf((py + 1.0f) * 0.5f, 0.0f), 1.0f) * 127.0f;
    float uz = fminf(fmaxf((pz + 1.0f) * 0.5f, 0.0f), 1.0f) * 127.0f;
    int x0 = min((int)floorf(ux), 126);
    int y0 = min((int)floorf(uy), 126);
    int z0 = min((int)floorf(uz), 126);
    float fx = ux - (float)x0, fy = uy - (float)y0, fz = uz - (float)z0;
    float gx = 1.0f - fx, gy = 1.0f - fy, gz = 1.0f - fz;

    int o000 = (x0*RES + y0)*RES + z0;
    int offs[8] = { o000, o000+1, o000+RES, o000+RES+1,
                    o000+RES*RES, o000+RES*RES+1, o000+RES*RES+RES, o000+RES*RES+RES+1 };
    float ws[8] = { gx*gy*gz, gx*gy*fz, gx*fy*gz, gx*fy*fz,
                    fx*gy*gz, fx*gy*fz, fx*fy*gz, fx*fy*fz };

    float L[16]; float N3[3];
    #pragma unroll
    for (int c = 0; c < 16; c++) L[c] = 0.0f;
    N3[0] = N3[1] = N3[2] = 0.0f;

    #pragma unroll
    for (int c = 0; c < 8; c++){
        int o = offs[c];
        float w = ws[c];
        uint4 pa = __ldg(&g_lat4[2*o]);
        uint4 pb = __ldg(&g_lat4[2*o+1]);
        uint2 pn = __ldg(&g_nrm2[o]);
        float2 f;
        f = h2f(pa.x); L[0]  += w*f.x; L[1]  += w*f.y;
        f = h2f(pa.y); L[2]  += w*f.x; L[3]  += w*f.y;
        f = h2f(pa.z); L[4]  += w*f.x; L[5]  += w*f.y;
        f = h2f(pa.w); L[6]  += w*f.x; L[7]  += w*f.y;
        f = h2f(pb.x); L[8]  += w*f.x; L[9]  += w*f.y;
        f = h2f(pb.y); L[10] += w*f.x; L[11] += w*f.y;
        f = h2f(pb.z); L[12] += w*f.x; L[13] += w*f.y;
        f = h2f(pb.w); L[14] += w*f.x; L[15] += w*f.y;
        f = h2f(pn.x); N3[0] += w*f.x; N3[1] += w*f.y;
        f = h2f(pn.y); N3[2] += w*f.x;
    }

    float nx = N3[0], ny = N3[1], nz = N3[2];
    float nl = sqrtf(nx*nx + ny*ny + nz*nz);
    float ninv = 1.0f / fmaxf(nl, 1e-12f);
    nx *= ninv; ny *= ninv; nz *= ninv;

    float d0 = L[0] + ACT_SHIFT;
    float sp = fmaxf(d0, 0.0f) + log1pf(__expf(-fabsf(d0)));
    g_alpha[idx] = 1.0f - __expf(-sp * 0.5f);
    g_nrm[idx] = nx; g_nrm[NTOT+idx] = ny; g_nrm[2*NTOT+idx] = nz;

    float vx = viewdirs[r*3], vy = viewdirs[r*3+1], vz = viewdirs[r*3+2];
    float vinv = rsqrtf(vx*vx + vy*vy + vz*vz);
    vx *= vinv; vy *= vinv; vz *= vinv;
    float dot = -(vx*nx + vy*ny + vz*nz);
    float rdx = 2.0f*dot*nx + vx, rdy = 2.0f*dot*ny + vy, rdz = 2.0f*dot*nz + vz;

    float fv[54];
    #pragma unroll
    for (int c = 0; c < 15; c++) fv[c] = L[c+1];
    fv[15] = rdx; fv[16] = rdy; fv[17] = rdz;
    float fq = 1.0f;
    #pragma unroll
    for (int k = 0; k < 6; k++){
        float sx, cx, sy, cy, sz, cz;
        __sincosf(fq*rdx, &sx, &cx);
        __sincosf(fq*rdy, &sy, &cy);
        __sincosf(fq*rdz, &sz, &cz);
        fv[18+3*k] = sx; fv[18+3*k+1] = sy; fv[18+3*k+2] = sz;
        fv[36+3*k] = cx; fv[36+3*k+1] = cy; fv[36+3*k+2] = cz;
        fq *= 2.0f;
    }
    #pragma unroll
    for (int kp = 0; kp < 27; kp++)
        g_feat2[kp*STRIDE + pos] = pack16(f2h(fv[2*kp]), f2h(fv[2*kp+1]));
    #pragma unroll
    for (int kp = 27; kp < 32; kp++)
        g_feat2[kp*STRIDE + pos] = 0;
}

// ---------------- kernel 2: single-pass fp16 HMMA MLP ------------------------
#define BF_OFF   0          // B frags: 3*8*4*32*8 = 24576
#define A_OFF    24576      // 128 rows * 144B = 18432
#define BIAS_OFF 43008      // b0,b1,b2 : 3*256
#define W3B_OFF  43776      // 192*4
#define B3_OFF   44544      // 16
#define SMEM_SZ  44560

__global__ __launch_bounds__(128) void k_mlp(
    const float* __restrict__ W0, const float* __restrict__ b0,
    const float* __restrict__ W1, const float* __restrict__ b1,
    const float* __restrict__ W2, const float* __restrict__ b2,
    const float* __restrict__ W3, const float* __restrict__ b3)
{
    __shared__ __align__(16) char smem[SMEM_SZ];
    int tid = threadIdx.x, wid = tid >> 5, lane = tid & 31;
    int gq = lane >> 2, t = lane & 3;
    int wbase = wid * 32;

    for (int i = tid; i < 3072; i += 128){
        int ln = i & 31, ks = (i >> 5) & 3, n = (i >> 7) & 7, L = i >> 10;
        int g = ln >> 2, tt = ln & 3;
        int col = 8*n + g;
        int k0 = 16*ks + 2*tt;
        unsigned short h[4];
        #pragma unroll
        for (int j = 0; j < 4; j++){
            int kk = k0 + (j >> 1)*8 + (j & 1);
            float v;
            if (L == 0)      v = (kk < 54) ? __ldg(W0 + kk*64 + col) : 0.0f;
            else if (L == 1) v = __ldg(W1 + kk*64 + col);
            else             v = __ldg(W2 + kk*64 + col);
            h[j] = f2h(v);
        }
        *(uint2*)(smem + BF_OFF + i*8) = make_uint2(pack16(h[0],h[1]), pack16(h[2],h[3]));
    }
    for (int i = tid; i < 192; i += 128) *(float*)(smem + W3B_OFF + 4*i) = W3[i];
    if (tid < 64){
        *(float*)(smem + BIAS_OFF        + 4*tid) = b0[tid];
        *(float*)(smem + BIAS_OFF + 256  + 4*tid) = b1[tid];
        *(float*)(smem + BIAS_OFF + 512  + 4*tid) = b2[tid];
    }
    if (tid < 3) *(float*)(smem + B3_OFF + 4*tid) = b3[tid];
    __syncthreads();

    int cnt    = g_count;
    int ntiles = (cnt + 127) >> 7;

    for (int tile = blockIdx.x; tile < ntiles; tile += gridDim.x){
        int tbase = tile << 7;

        #pragma unroll 8
        for (int j = 0; j < 32; j++){
            uint32_t v = g_feat2[j*STRIDE + tbase + tid];
            *(uint32_t*)(smem + A_OFF + tid*144 + j*4) = v;
        }
        __syncthreads();

        uint32_t ah[2][4][4];
        #pragma unroll
        for (int m = 0; m < 2; m++){
            int R = wbase + 16*m + gq;
            #pragma unroll
            for (int ks = 0; ks < 4; ks++){
                int base = A_OFF + R*144 + 32*ks + 4*t;
                ah[m][ks][0] = *(uint32_t*)(smem + base);
                ah[m][ks][1] = *(uint32_t*)(smem + base + 8*144);
                ah[m][ks][2] = *(uint32_t*)(smem + base + 16);
                ah[m][ks][3] = *(uint32_t*)(smem + base + 8*144 + 16);
            }
        }
        __syncthreads();

        float rgbq[4][3];

        #pragma unroll 1
        for (int L = 0; L < 3; L++){
            float acc[2][8][4];
            #pragma unroll
            for (int m = 0; m < 2; m++)
                #pragma unroll
                for (int n = 0; n < 8; n++)
                    #pragma unroll
                    for (int j = 0; j < 4; j++) acc[m][n][j] = 0.0f;

            #pragma unroll
            for (int ks = 0; ks < 4; ks++){
                uint2 B[8];
                #pragma unroll
                for (int n = 0; n < 8; n++)
                    B[n] = *(uint2*)(smem + BF_OFF + ((((L*8 + n)*4 + ks)*32 + lane)*8));
                #pragma unroll
                for (int n = 0; n < 8; n++){
                    mma_fp16(acc[0][n], ah[0][ks][0], ah[0][ks][1], ah[0][ks][2], ah[0][ks][3], B[n].x, B[n].y);
                    mma_fp16(acc[1][n], ah[1][ks][0], ah[1][ks][1], ah[1][ks][2], ah[1][ks][3], B[n].x, B[n].y);
                }
            }

            if (L < 2){
                #pragma unroll
                for (int m = 0; m < 2; m++)
                    #pragma unroll
                    for (int n = 0; n < 8; n++){
                        float2 bb = *(float2*)(smem + BIAS_OFF + L*256 + (8*n + 2*t)*4);
                        float v0 = fmaxf(acc[m][n][0] + bb.x, 0.0f);
                        float v1 = fmaxf(acc[m][n][1] + bb.y, 0.0f);
                        float v2 = fmaxf(acc[m][n][2] + bb.x, 0.0f);
                        float v3 = fmaxf(acc[m][n][3] + bb.y, 0.0f);
                        int ks = n >> 1, w = (n & 1)*2;
                        ah[m][ks][w]   = pack16(f2h(v0), f2h(v1));
                        ah[m][ks][w+1] = pack16(f2h(v2), f2h(v3));
                    }
            } else {
                const float* w3 = (const float*)(smem + W3B_OFF);
                #pragma unroll
                for (int sl = 0; sl < 4; sl++){ rgbq[sl][0]=0.f; rgbq[sl][1]=0.f; rgbq[sl][2]=0.f; }
                #pragma unroll
                for (int m = 0; m < 2; m++)
                    #pragma unroll
                    for (int n = 0; n < 8; n++){
                        int col0 = n*8 + 2*t;
                        float2 bb = *(float2*)(smem + BIAS_OFF + 512 + col0*4);
                        float v0 = fmaxf(acc[m][n][0] + bb.x, 0.0f);
                        float v1 = fmaxf(acc[m][n][1] + bb.y, 0.0f);
                        float v2 = fmaxf(acc[m][n][2] + bb.x, 0.0f);
                        float v3 = fmaxf(acc[m][n][3] + bb.y, 0.0f);
                        #pragma unroll
                        for (int c = 0; c < 3; c++){
                            rgbq[2*m  ][c] += v0*w3[col0*3+c] + v1*w3[(col0+1)*3+c];
                            rgbq[2*m+1][c] += v2*w3[col0*3+c] + v3*w3[(col0+1)*3+c];
                        }
                    }
            }
        }

        #pragma unroll
        for (int sl = 0; sl < 4; sl++)
            #pragma unroll
            for (int c = 0; c < 3; c++){
                float v = rgbq[sl][c];
                v += __shfl_xor_sync(0xffffffffu, v, 1);
                v += __shfl_xor_sync(0xffffffffu, v, 2);
                rgbq[sl][c] = v;
            }
        if (t == 0){
            const float* bb3 = (const float*)(smem + B3_OFF);
            #pragma unroll
            for (int sl = 0; sl < 4; sl++){
                int m = sl >> 1, h = sl & 1;
                int gi = tbase + wbase + m*16 + gq + 8*h;
                if (gi < cnt){
                    int sidx = g_sidx[gi];
                    g_rgb[sidx]        = 1.0f/(1.0f + __expf(-(rgbq[sl][0] + bb3[0])));
                    g_rgb[NTOT+sidx]   = 1.0f/(1.0f + __expf(-(rgbq[sl][1] + bb3[1])));
                    g_rgb[2*NTOT+sidx] = 1.0f/(1.0f + __expf(-(rgbq[sl][2] + bb3[2])));
                }
            }
        }
    }
}

// ---------------- kernel 3: warp-per-ray composite (parallel chunk scans) ----
__global__ __launch_bounds__(128) void k_perray(float* __restrict__ out)
{
    int gtid = blockIdx.x * 128 + threadIdx.x;
    if (gtid == 0) g_count = 0;  // reset for next replay
    int r    = gtid >> 5;
    int lane = threadIdx.x & 31;

    float *o_rgb   = out;
    float *o_depth = out + 12288;
    float *o_disp  = out + 16384;
    float *o_acc   = out + 20480;
    float *o_nrm   = out + 24576;
    float *o_w     = out + 36864;
    float *o_ai    = out + 1085440;

    int base = r << 8;

    // 1) load all alphas (independent)
    float alp[8], v[8];
    #pragma unroll
    for (int c = 0; c < 8; c++) alp[c] = g_alpha[base + c*32 + lane];
    #pragma unroll
    for (int c = 0; c < 8; c++) v[c] = fmaxf(1.0f - alp[c], 1e-10f);

    // 2) eight interleaved inclusive warp scans (ILP across chunks)
    #pragma unroll
    for (int off = 1; off < 32; off <<= 1){
        float o[8];
        #pragma unroll
        for (int c = 0; c < 8; c++) o[c] = __shfl_up_sync(0xffffffffu, v[c], off);
        #pragma unroll
        for (int c = 0; c < 8; c++) if (lane >= off) v[c] *= o[c];
    }

    // 3) chunk totals + serial prefix (8 scalar multiplies)
    float tot[8], Pc[8];
    #pragma unroll
    for (int c = 0; c < 8; c++) tot[c] = __shfl_sync(0xffffffffu, v[c], 31);
    float P = 1.0f;
    #pragma unroll
    for (int c = 0; c < 8; c++){ Pc[c] = P; P *= tot[c]; }

    // 4) weights + stores
    float pv[8], w[8];
    #pragma unroll
    for (int c = 0; c < 8; c++) pv[c] = __shfl_up_sync(0xffffffffu, v[c], 1);
    #pragma unroll
    for (int c = 0; c < 8; c++){
        float excl = lane ? Pc[c]*pv[c] : Pc[c];
        w[c] = alp[c]*excl;
        int idx = base + c*32 + lane;
        o_w[idx]                    = w[c];
        o_ai[r*257 + 1 + c*32+lane] = Pc[c]*v[c];
    }

    // 5) weighted sums (48 independent loads)
    float sr0=0.f, sr1=0.f, sr2=0.f, sd=0.f, sa=0.f, sn0=0.f, sn1=0.f, sn2=0.f;
    #pragma unroll
    for (int c = 0; c < 8; c++){
        int idx = base + c*32 + lane;
        float t = T0 + (float)(c*32+lane) * DT;
        sd  += w[c]*t;  sa += w[c];
        sr0 += w[c]*g_rgb[idx]; sr1 += w[c]*g_rgb[NTOT+idx]; sr2 += w[c]*g_rgb[2*NTOT+idx];
        sn0 += w[c]*g_nrm[idx]; sn1 += w[c]*g_nrm[NTOT+idx]; sn2 += w[c]*g_nrm[2*NTOT+idx];
    }
    #pragma unroll
    for (int off = 16; off; off >>= 1){
        sr0 += __shfl_xor_sync(0xffffffffu, sr0, off);
        sr1 += __shfl_xor_sync(0xffffffffu, sr1, off);
        sr2 += __shfl_xor_sync(0xffffffffu, sr2, off);
        sd  += __shfl_xor_sync(0xffffffffu, sd,  off);
        sa  += __shfl_xor_sync(0xffffffffu, sa,  off);
        sn0 += __shfl_xor_sync(0xffffffffu, sn0, off);
        sn1 += __shfl_xor_sync(0xffffffffu, sn1, off);
        sn2 += __shfl_xor_sync(0xffffffffu, sn2, off);
    }
    if (lane == 0){
        o_rgb[r*3]   = sr0 + P;
        o_rgb[r*3+1] = sr1 + P;
        o_rgb[r*3+2] = sr2 + P;
        float dm = sd + P * 3.0f;
        o_depth[r] = dm;
        o_disp[r]  = 1.0f / dm;
        o_acc[r]   = sa;
        o_nrm[r*3]   = sn0;
        o_nrm[r*3+1] = sn1;
        o_nrm[r*3+2] = sn2;
        o_ai[r*257]  = 1.0f;
    }
}

extern "C" void kernel_launch(void* const* d_in, const int* in_sizes, int n_in,
                              void* d_out, int out_size)
{
    const float* rays_o   = (const float*)d_in[0];
    const float* rays_d   = (const float*)d_in[1];
    const float* viewdirs = (const float*)d_in[2];
    const float* lat_grid = (const float*)d_in[3];
    const float* nrm_grid = (const float*)d_in[4];
    const float* W0 = (const float*)d_in[5];
    const float* b0 = (const float*)d_in[6];
    const float* W1 = (const float*)d_in[7];
    const float* b1 = (const float*)d_in[8];
    const float* W2 = (const float*)d_in[9];
    const float* b2 = (const float*)d_in[10];
    const float* W3 = (const float*)d_in[11];
    const float* b3 = (const float*)d_in[12];

    k_xpose<<<RES3/512, 256>>>(lat_grid, nrm_grid);
    k_feat<<<NTOT/128, 128>>>(rays_o, rays_d, viewdirs);
    k_mlp<<<592, 128>>>(W0, b0, W1, b1, W2, b2, W3, b3);
    k_perray<<<NRAYS*32/128, 128>>>((float*)d_out);
}

// round 7
// speedup vs baseline: 5.2347x; 1.0227x over previous
#include <cuda_runtime.h>
#include <cuda_fp16.h>
#include <math.h>
#include <stdint.h>

#define NRAYS 4096
#define NSAMP 256
#define NTOT  (NRAYS*NSAMP)
#define STRIDE (NTOT + 128)
#define RES   128
#define RES3  (RES*RES*RES)
#define T0    0.2f
#define DT    (2.8f/255.0f)
#define ACT_SHIFT (-4.595119850134589f)

// ---------------- scratch ----------------------------------------------------
__device__ float    g_alpha[NTOT];
__device__ float    g_rgb[3*NTOT];
__device__ float    g_nrm[3*NTOT];
__device__ uint4    g_lat4[2*RES3];     // 16 fp16 latent channels per voxel
__device__ uint2    g_nrm2[RES3];       // nx,ny,nz fp16 + pad
__device__ uint4    g_featr[STRIDE*8];  // row-major: 64 fp16 features per sample (128B row)
__device__ int      g_sidx[STRIDE];
__device__ int      g_count;

// ---------------- helpers ----------------------------------------------------
__device__ __forceinline__ uint32_t pack16(unsigned short lo, unsigned short hi){
    return (uint32_t)lo | ((uint32_t)hi << 16);
}
__device__ __forceinline__ unsigned short f2h(float v){
    return __half_as_ushort(__float2half_rn(v));
}
__device__ __forceinline__ uint32_t packh2(float a, float b){
    __half2 h = __floats2half2_rn(a, b);
    return *(uint32_t*)&h;
}
__device__ __forceinline__ float2 h2f(uint32_t u){
    __half2 h = *reinterpret_cast<__half2*>(&u);
    return __half22float2(h);
}
__device__ __forceinline__ void mma_fp16(float* d, uint32_t a0, uint32_t a1,
                                         uint32_t a2, uint32_t a3,
                                         uint32_t b0, uint32_t b1){
    asm volatile(
        "mma.sync.aligned.m16n8k16.row.col.f32.f16.f16.f32 "
        "{%0,%1,%2,%3}, {%4,%5,%6,%7}, {%8,%9}, {%0,%1,%2,%3};"
        : "+f"(d[0]), "+f"(d[1]), "+f"(d[2]), "+f"(d[3])
        : "r"(a0), "r"(a1), "r"(a2), "r"(a3), "r"(b0), "r"(b1));
}

// ---------------- kernel 0: grid transpose (2 voxels/thread) -----------------
__global__ __launch_bounds__(256) void k_xpose(
    const float* __restrict__ lat, const float* __restrict__ nrm)
{
    int v2 = blockIdx.x * 256 + threadIdx.x;
    unsigned short ha[16], hb[16];
    #pragma unroll
    for (int c = 0; c < 16; c++){
        float2 f = __ldg((const float2*)(lat + c*RES3) + v2);
        ha[c] = f2h(f.x); hb[c] = f2h(f.y);
    }
    uint4 w0, w1, w2, w3;
    w0.x = pack16(ha[0],ha[1]);   w0.y = pack16(ha[2],ha[3]);
    w0.z = pack16(ha[4],ha[5]);   w0.w = pack16(ha[6],ha[7]);
    w1.x = pack16(ha[8],ha[9]);   w1.y = pack16(ha[10],ha[11]);
    w1.z = pack16(ha[12],ha[13]); w1.w = pack16(ha[14],ha[15]);
    w2.x = pack16(hb[0],hb[1]);   w2.y = pack16(hb[2],hb[3]);
    w2.z = pack16(hb[4],hb[5]);   w2.w = pack16(hb[6],hb[7]);
    w3.x = pack16(hb[8],hb[9]);   w3.y = pack16(hb[10],hb[11]);
    w3.z = pack16(hb[12],hb[13]); w3.w = pack16(hb[14],hb[15]);
    g_lat4[4*v2]   = w0;
    g_lat4[4*v2+1] = w1;
    g_lat4[4*v2+2] = w2;
    g_lat4[4*v2+3] = w3;
    float2 n0 = __ldg((const float2*)(nrm)            + v2);
    float2 n1 = __ldg((const float2*)(nrm +   RES3)   + v2);
    float2 n2 = __ldg((const float2*)(nrm + 2*RES3)   + v2);
    uint4 nq;
    nq.x = pack16(f2h(n0.x), f2h(n1.x));
    nq.y = pack16(f2h(n2.x), 0);
    nq.z = pack16(f2h(n0.y), f2h(n1.y));
    nq.w = pack16(f2h(n2.y), 0);
    ((uint4*)g_nrm2)[v2] = nq;
}

// ---------------- kernel 1: featurize + compact ------------------------------
__global__ __launch_bounds__(128) void k_feat(
    const float* __restrict__ rays_o, const float* __restrict__ rays_d,
    const float* __restrict__ viewdirs)
{
    int idx  = blockIdx.x * 128 + threadIdx.x;
    int r    = idx >> 8, s = idx & 255;
    int lane = threadIdx.x & 31;

    float ox = rays_o[r*3], oy = rays_o[r*3+1], oz = rays_o[r*3+2];
    float dx = rays_d[r*3], dy = rays_d[r*3+1], dz = rays_d[r*3+2];
    float dinv = rsqrtf(dx*dx + dy*dy + dz*dz);
    dx *= dinv; dy *= dinv; dz *= dinv;

    float t  = T0 + (float)s * DT;
    float px = ox + dx*t, py = oy + dy*t, pz = oz + dz*t;

    bool inb = (px >= -1.0f) & (px <= 1.0f) & (py >= -1.0f) & (py <= 1.0f)
             & (pz >= -1.0f) & (pz <= 1.0f);

    unsigned mask = __ballot_sync(0xffffffffu, inb);
    int base = 0;
    if (mask){
        if (lane == 0) base = atomicAdd(&g_count, __popc(mask));
        base = __shfl_sync(0xffffffffu, base, 0);
    }
    if (!inb){ g_alpha[idx] = 0.0f; return; }
    int pos = base + __popc(mask & ((1u << lane) - 1u));
    g_sidx[pos] = idx;

    float ux = fminf(fmaxf((px + 1.0f) * 0.5f, 0.0f), 1.0f) * 127.0f;
    float uy = fminf(fmaxf((py + 1.0f) * 0.5f, 0.0f), 1.0f) * 127.0f;
    float uz = fminf(fmaxf((pz + 1.0f) * 0.5f, 0.0f), 1.0f) * 127.0f;
    int x0 = min((int)floorf(ux), 126);
    int y0 = min((int)floorf(uy), 126);
    int z0 = min((int)floorf(uz), 126);
    float fx = ux - (float)x0, fy = uy - (float)y0, fz = uz - (float)z0;
    float gx = 1.0f - fx, gy = 1.0f - fy, gz = 1.0f - fz;

    int o000 = (x0*RES + y0)*RES + z0;
    int offs[8] = { o000, o000+1, o000+RES, o000+RES+1,
                    o000+RES*RES, o000+RES*RES+1, o000+RES*RES+RES, o000+RES*RES+RES+1 };
    float ws[8] = { gx*gy*gz, gx*gy*fz, gx*fy*gz, gx*fy*fz,
                    fx*gy*gz, fx*gy*fz, fx*fy*gz, fx*fy*fz };

    float L[16]; float N3[3];
    #pragma unroll
    for (int c = 0; c < 16; c++) L[c] = 0.0f;
    N3[0] = N3[1] = N3[2] = 0.0f;

    #pragma unroll
    for (int c = 0; c < 8; c++){
        int o = offs[c];
        float w = ws[c];
        uint4 pa = __ldg(&g_lat4[2*o]);
        uint4 pb = __ldg(&g_lat4[2*o+1]);
        uint2 pn = __ldg(&g_nrm2[o]);
        float2 f;
        f = h2f(pa.x); L[0]  += w*f.x; L[1]  += w*f.y;
        f = h2f(pa.y); L[2]  += w*f.x; L[3]  += w*f.y;
        f = h2f(pa.z); L[4]  += w*f.x; L[5]  += w*f.y;
        f = h2f(pa.w); L[6]  += w*f.x; L[7]  += w*f.y;
        f = h2f(pb.x); L[8]  += w*f.x; L[9]  += w*f.y;
        f = h2f(pb.y); L[10] += w*f.x; L[11] += w*f.y;
        f = h2f(pb.z); L[12] += w*f.x; L[13] += w*f.y;
        f = h2f(pb.w); L[14] += w*f.x; L[15] += w*f.y;
        f = h2f(pn.x); N3[0] += w*f.x; N3[1] += w*f.y;
        f = h2f(pn.y); N3[2] += w*f.x;
    }

    float nx = N3[0], ny = N3[1], nz = N3[2];
    float nl = sqrtf(nx*nx + ny*ny + nz*nz);
    float ninv = 1.0f / fmaxf(nl, 1e-12f);
    nx *= ninv; ny *= ninv; nz *= ninv;

    float d0 = L[0] + ACT_SHIFT;
    float sp = fmaxf(d0, 0.0f) + log1pf(__expf(-fabsf(d0)));
    g_alpha[idx] = 1.0f - __expf(-sp * 0.5f);
    g_nrm[idx] = nx; g_nrm[NTOT+idx] = ny; g_nrm[2*NTOT+idx] = nz;

    float vx = viewdirs[r*3], vy = viewdirs[r*3+1], vz = viewdirs[r*3+2];
    float vinv = rsqrtf(vx*vx + vy*vy + vz*vz);
    vx *= vinv; vy *= vinv; vz *= vinv;
    float dot = -(vx*nx + vy*ny + vz*nz);
    float rdx = 2.0f*dot*nx + vx, rdy = 2.0f*dot*ny + vy, rdz = 2.0f*dot*nz + vz;

    float fv[54];
    #pragma unroll
    for (int c = 0; c < 15; c++) fv[c] = L[c+1];
    fv[15] = rdx; fv[16] = rdy; fv[17] = rdz;
    float fq = 1.0f;
    #pragma unroll
    for (int k = 0; k < 6; k++){
        float sx, cx, sy, cy, sz, cz;
        __sincosf(fq*rdx, &sx, &cx);
        __sincosf(fq*rdy, &sy, &cy);
        __sincosf(fq*rdz, &sz, &cz);
        fv[18+3*k] = sx; fv[18+3*k+1] = sy; fv[18+3*k+2] = sz;
        fv[36+3*k] = cx; fv[36+3*k+1] = cy; fv[36+3*k+2] = cz;
        fq *= 2.0f;
    }
    uint32_t fw[32];
    #pragma unroll
    for (int w = 0; w < 27; w++) fw[w] = packh2(fv[2*w], fv[2*w+1]);
    #pragma unroll
    for (int w = 27; w < 32; w++) fw[w] = 0;
    uint4* dst = g_featr + pos*8;
    #pragma unroll
    for (int i = 0; i < 8; i++)
        dst[i] = make_uint4(fw[4*i], fw[4*i+1], fw[4*i+2], fw[4*i+3]);
}

// ---------------- kernel 2: single-pass fp16 HMMA MLP (sync-free tiles) ------
#define BF_OFF   0          // B frags: 3*8*4*32*8 = 24576
#define BIAS_OFF 24576      // b0,b1,b2 : 3*256
#define W3B_OFF  25344      // 192*4
#define B3_OFF   26112      // 16
#define SMEM_SZ  26128

__global__ __launch_bounds__(128) void k_mlp(
    const float* __restrict__ W0, const float* __restrict__ b0,
    const float* __restrict__ W1, const float* __restrict__ b1,
    const float* __restrict__ W2, const float* __restrict__ b2,
    const float* __restrict__ W3, const float* __restrict__ b3)
{
    __shared__ __align__(16) char smem[SMEM_SZ];
    int tid = threadIdx.x, wid = tid >> 5, lane = tid & 31;
    int gq = lane >> 2, t = lane & 3;
    int wbase = wid * 32;

    for (int i = tid; i < 3072; i += 128){
        int ln = i & 31, ks = (i >> 5) & 3, n = (i >> 7) & 7, L = i >> 10;
        int g = ln >> 2, tt = ln & 3;
        int col = 8*n + g;
        int k0 = 16*ks + 2*tt;
        unsigned short h[4];
        #pragma unroll
        for (int j = 0; j < 4; j++){
            int kk = k0 + (j >> 1)*8 + (j & 1);
            float v;
            if (L == 0)      v = (kk < 54) ? __ldg(W0 + kk*64 + col) : 0.0f;
            else if (L == 1) v = __ldg(W1 + kk*64 + col);
            else             v = __ldg(W2 + kk*64 + col);
            h[j] = f2h(v);
        }
        *(uint2*)(smem + BF_OFF + i*8) = make_uint2(pack16(h[0],h[1]), pack16(h[2],h[3]));
    }
    for (int i = tid; i < 192; i += 128) *(float*)(smem + W3B_OFF + 4*i) = W3[i];
    if (tid < 64){
        *(float*)(smem + BIAS_OFF        + 4*tid) = b0[tid];
        *(float*)(smem + BIAS_OFF + 256  + 4*tid) = b1[tid];
        *(float*)(smem + BIAS_OFF + 512  + 4*tid) = b2[tid];
    }
    if (tid < 3) *(float*)(smem + B3_OFF + 4*tid) = b3[tid];
    __syncthreads();

    int cnt    = g_count;
    int ntiles = (cnt + 127) >> 7;
    const uint32_t* fwp = (const uint32_t*)g_featr;

    for (int tile = blockIdx.x; tile < ntiles; tile += gridDim.x){
        int tbase = tile << 7;

        // A fragments: direct gmem -> registers
        uint32_t ah[2][4][4];
        #pragma unroll
        for (int m = 0; m < 2; m++){
            int r0 = (tbase + wbase + 16*m + gq) * 32;
            int r1 = r0 + 8*32;
            #pragma unroll
            for (int ks = 0; ks < 4; ks++){
                ah[m][ks][0] = __ldg(fwp + r0 + 8*ks + t);
                ah[m][ks][1] = __ldg(fwp + r1 + 8*ks + t);
                ah[m][ks][2] = __ldg(fwp + r0 + 8*ks + t + 4);
                ah[m][ks][3] = __ldg(fwp + r1 + 8*ks + t + 4);
            }
        }

        float rgbq[4][3];

        #pragma unroll 1
        for (int L = 0; L < 3; L++){
            float acc[2][8][4];
            #pragma unroll
            for (int m = 0; m < 2; m++)
                #pragma unroll
                for (int n = 0; n < 8; n++)
                    #pragma unroll
                    for (int j = 0; j < 4; j++) acc[m][n][j] = 0.0f;

            #pragma unroll
            for (int ks = 0; ks < 4; ks++){
                uint2 B[8];
                #pragma unroll
                for (int n = 0; n < 8; n++)
                    B[n] = *(uint2*)(smem + BF_OFF + ((((L*8 + n)*4 + ks)*32 + lane)*8));
                #pragma unroll
                for (int n = 0; n < 8; n++){
                    mma_fp16(acc[0][n], ah[0][ks][0], ah[0][ks][1], ah[0][ks][2], ah[0][ks][3], B[n].x, B[n].y);
                    mma_fp16(acc[1][n], ah[1][ks][0], ah[1][ks][1], ah[1][ks][2], ah[1][ks][3], B[n].x, B[n].y);
                }
            }

            if (L < 2){
                #pragma unroll
                for (int m = 0; m < 2; m++)
                    #pragma unroll
                    for (int n = 0; n < 8; n++){
                        float2 bb = *(float2*)(smem + BIAS_OFF + L*256 + (8*n + 2*t)*4);
                        float v0 = fmaxf(acc[m][n][0] + bb.x, 0.0f);
                        float v1 = fmaxf(acc[m][n][1] + bb.y, 0.0f);
                        float v2 = fmaxf(acc[m][n][2] + bb.x, 0.0f);
                        float v3 = fmaxf(acc[m][n][3] + bb.y, 0.0f);
                        int ks = n >> 1, w = (n & 1)*2;
                        ah[m][ks][w]   = packh2(v0, v1);
                        ah[m][ks][w+1] = packh2(v2, v3);
                    }
            } else {
                const float* w3 = (const float*)(smem + W3B_OFF);
                #pragma unroll
                for (int sl = 0; sl < 4; sl++){ rgbq[sl][0]=0.f; rgbq[sl][1]=0.f; rgbq[sl][2]=0.f; }
                #pragma unroll
                for (int m = 0; m < 2; m++)
                    #pragma unroll
                    for (int n = 0; n < 8; n++){
                        int col0 = n*8 + 2*t;
                        float2 bb = *(float2*)(smem + BIAS_OFF + 512 + col0*4);
                        float v0 = fmaxf(acc[m][n][0] + bb.x, 0.0f);
                        float v1 = fmaxf(acc[m][n][1] + bb.y, 0.0f);
                        float v2 = fmaxf(acc[m][n][2] + bb.x, 0.0f);
                        float v3 = fmaxf(acc[m][n][3] + bb.y, 0.0f);
                        #pragma unroll
                        for (int c = 0; c < 3; c++){
                            rgbq[2*m  ][c] += v0*w3[col0*3+c] + v1*w3[(col0+1)*3+c];
                            rgbq[2*m+1][c] += v2*w3[col0*3+c] + v3*w3[(col0+1)*3+c];
                        }
                    }
            }
        }

        #pragma unroll
        for (int sl = 0; sl < 4; sl++)
            #pragma unroll
            for (int c = 0; c < 3; c++){
                float v = rgbq[sl][c];
                v += __shfl_xor_sync(0xffffffffu, v, 1);
                v += __shfl_xor_sync(0xffffffffu, v, 2);
                rgbq[sl][c] = v;
            }
        if (t == 0){
            const float* bb3 = (const float*)(smem + B3_OFF);
            #pragma unroll
            for (int sl = 0; sl < 4; sl++){
                int m = sl >> 1, h = sl & 1;
                int gi = tbase + wbase + m*16 + gq + 8*h;
                if (gi < cnt){
                    int sidx = g_sidx[gi];
                    g_rgb[sidx]        = 1.0f/(1.0f + __expf(-(rgbq[sl][0] + bb3[0])));
                    g_rgb[NTOT+sidx]   = 1.0f/(1.0f + __expf(-(rgbq[sl][1] + bb3[1])));
                    g_rgb[2*NTOT+sidx] = 1.0f/(1.0f + __expf(-(rgbq[sl][2] + bb3[2])));
                }
            }
        }
    }
}

// ---------------- kernel 3: warp-per-ray composite (parallel chunk scans) ----
__global__ __launch_bounds__(128) void k_perray(float* __restrict__ out)
{
    int gtid = blockIdx.x * 128 + threadIdx.x;
    if (gtid == 0) g_count = 0;  // reset for next replay
    int r    = gtid >> 5;
    int lane = threadIdx.x & 31;

    float *o_rgb   = out;
    float *o_depth = out + 12288;
    float *o_disp  = out + 16384;
    float *o_acc   = out + 20480;
    float *o_nrm   = out + 24576;
    float *o_w     = out + 36864;
    float *o_ai    = out + 1085440;

    int base = r << 8;

    float alp[8], v[8];
    #pragma unroll
    for (int c = 0; c < 8; c++) alp[c] = g_alpha[base + c*32 + lane];
    #pragma unroll
    for (int c = 0; c < 8; c++) v[c] = fmaxf(1.0f - alp[c], 1e-10f);

    #pragma unroll
    for (int off = 1; off < 32; off <<= 1){
        float o[8];
        #pragma unroll
        for (int c = 0; c < 8; c++) o[c] = __shfl_up_sync(0xffffffffu, v[c], off);
        #pragma unroll
        for (int c = 0; c < 8; c++) if (lane >= off) v[c] *= o[c];
    }

    float tot[8], Pc[8];
    #pragma unroll
    for (int c = 0; c < 8; c++) tot[c] = __shfl_sync(0xffffffffu, v[c], 31);
    float P = 1.0f;
    #pragma unroll
    for (int c = 0; c < 8; c++){ Pc[c] = P; P *= tot[c]; }

    float pv[8], w[8];
    #pragma unroll
    for (int c = 0; c < 8; c++) pv[c] = __shfl_up_sync(0xffffffffu, v[c], 1);
    #pragma unroll
    for (int c = 0; c < 8; c++){
        float excl = lane ? Pc[c]*pv[c] : Pc[c];
        w[c] = alp[c]*excl;
        int idx = base + c*32 + lane;
        o_w[idx]                    = w[c];
        o_ai[r*257 + 1 + c*32+lane] = Pc[c]*v[c];
    }

    float sr0=0.f, sr1=0.f, sr2=0.f, sd=0.f, sa=0.f, sn0=0.f, sn1=0.f, sn2=0.f;
    #pragma unroll
    for (int c = 0; c < 8; c++){
        int idx = base + c*32 + lane;
        float t = T0 + (float)(c*32+lane) * DT;
        sd  += w[c]*t;  sa += w[c];
        sr0 += w[c]*g_rgb[idx]; sr1 += w[c]*g_rgb[NTOT+idx]; sr2 += w[c]*g_rgb[2*NTOT+idx];
        sn0 += w[c]*g_nrm[idx]; sn1 += w[c]*g_nrm[NTOT+idx]; sn2 += w[c]*g_nrm[2*NTOT+idx];
    }
    #pragma unroll
    for (int off = 16; off; off >>= 1){
        sr0 += __shfl_xor_sync(0xffffffffu, sr0, off);
        sr1 += __shfl_xor_sync(0xffffffffu, sr1, off);
        sr2 += __shfl_xor_sync(0xffffffffu, sr2, off);
        sd  += __shfl_xor_sync(0xffffffffu, sd,  off);
        sa  += __shfl_xor_sync(0xffffffffu, sa,  off);
        sn0 += __shfl_xor_sync(0xffffffffu, sn0, off);
        sn1 += __shfl_xor_sync(0xffffffffu, sn1, off);
        sn2 += __shfl_xor_sync(0xffffffffu, sn2, off);
    }
    if (lane == 0){
        o_rgb[r*3]   = sr0 + P;
        o_rgb[r*3+1] = sr1 + P;
        o_rgb[r*3+2] = sr2 + P;
        float dm = sd + P * 3.0f;
        o_depth[r] = dm;
        o_disp[r]  = 1.0f / dm;
        o_acc[r]   = sa;
        o_nrm[r*3]   = sn0;
        o_nrm[r*3+1] = sn1;
        o_nrm[r*3+2] = sn2;
        o_ai[r*257]  = 1.0f;
    }
}

extern "C" void kernel_launch(void* const* d_in, const int* in_sizes, int n_in,
                              void* d_out, int out_size)
{
    const float* rays_o   = (const float*)d_in[0];
    const float* rays_d   = (const float*)d_in[1];
    const float* viewdirs = (const float*)d_in[2];
    const float* lat_grid = (const float*)d_in[3];
    const float* nrm_grid = (const float*)d_in[4];
    const float* W0 = (const float*)d_in[5];
    const float* b0 = (const float*)d_in[6];
    const float* W1 = (const float*)d_in[7];
    const float* b1 = (const float*)d_in[8];
    const float* W2 = (const float*)d_in[9];
    const float* b2 = (const float*)d_in[10];
    const float* W3 = (const float*)d_in[11];
    const float* b3 = (const float*)d_in[12];

    k_xpose<<<RES3/512, 256>>>(lat_grid, nrm_grid);
    k_feat<<<NTOT/128, 128>>>(rays_o, rays_d, viewdirs);
    k_mlp<<<592, 128>>>(W0, b0, W1, b1, W2, b2, W3, b3);
    k_perray<<<NRAYS*32/128, 128>>>((float*)d_out);
}